// round 11
// baseline (speedup 1.0000x reference)
#include <cuda_runtime.h>
#include <cuda_bf16.h>

#define BSZ 32
#define TT  200
#define RR  512
#define FF  128
#define BR  4
#define CC  10
#define K2  1024
#define NROWS 2048
#define VTH 0.5f

#define NCTA_TOTAL 148
#define GEMM_CTAS  128
#define NTH 1024

#define KT_STRIDE 36
#define KT_STRIDE_B 144
#define ROWSTRIDE 272     // cur section + spk section, each padded to 8
#define OUT0 (BSZ*CC*TT)

// -------- device scratch --------
__device__ float    g_currents[TT * RR * BSZ];     // [T][R][B]
__device__ float    g_projA[TT * NROWS * BSZ];     // [T][row][B] precomputed cur-proj
__device__ float    g_spk[2][RR * BSZ];            // [R][B] ping-pong
__device__ unsigned g_pidx[NROWS * ROWSTRIDE];     // byte offsets into kT halves
__device__ float    g_wv [NROWS * ROWSTRIDE];
__device__ unsigned g_secs[NROWS];                 // ncurP | nspkP<<16
__device__ volatile unsigned g_arrive[160];        // 0..127 gemm, 128..147 readout

__device__ __forceinline__ float sigmoidf_(float x) { return 1.f / (1.f + __expf(-x)); }

__global__ void k_init() {
    int tid = blockIdx.x * blockDim.x + threadIdx.x;
    int n = 2 * RR * BSZ;
    for (int i = tid; i < n; i += gridDim.x * blockDim.x) ((float*)g_spk)[i] = 0.f;
    if (tid < 160) g_arrive[tid] = (tid < 148) ? 0u : 0x7FFFFFFFu;
}

__global__ void k_currents(const float* __restrict__ inp,
                           const float* __restrict__ w_in,
                           const float* __restrict__ b_in) {
    __shared__ float sw[FF];
    int tid = threadIdx.x;
    if (tid < FF) sw[tid] = w_in[tid];
    __syncthreads();
    int lane = tid & 31, wid = tid >> 5;
    long long rid = (long long)blockIdx.x * 8 + wid;
    if (rid >= (long long)BSZ * TT * RR) return;
    const float4* p = (const float4*)inp + rid * (FF / 4);
    float4 v = p[lane];
    float4 w = ((const float4*)sw)[lane];
    float s = v.x * w.x + v.y * w.y + v.z * w.z + v.w * w.w;
    #pragma unroll
    for (int o = 16; o; o >>= 1) s += __shfl_xor_sync(0xffffffffu, s, o);
    if (lane == 0) {
        int r = (int)(rid % RR);
        long long bt = rid / RR;
        int t = (int)(bt % TT);
        int b = (int)(bt / TT);
        g_currents[((long long)t * RR + r) * BSZ + b] = s + b_in[0];
    }
}

// compact rows: cur section (k<512, off k*144) then spk section (k>=512, off (k-512)*144)
__global__ void k_prep(const float* __restrict__ w_rnn,
                       const float* __restrict__ mask) {
    int row = blockIdx.x * 8 + (threadIdx.x >> 5);
    int lane = threadIdx.x & 31;
    if (row >= NROWS) return;
    unsigned* pp = g_pidx + row * ROWSTRIDE;
    float*    wp = g_wv  + row * ROWSTRIDE;

    int base = 0;
    for (int c0 = 0; c0 < 512; c0 += 32) {
        float m = mask[(long long)row * K2 + c0 + lane];
        unsigned bal = __ballot_sync(0xffffffffu, m != 0.f);
        int pre = __popc(bal & ((1u << lane) - 1u));
        if (m != 0.f) {
            pp[base + pre] = (unsigned)(c0 + lane) * KT_STRIDE_B;
            wp[base + pre] = w_rnn[(long long)row * K2 + c0 + lane];
        }
        base += __popc(bal);
    }
    int ncur = base, ncurP = (ncur + 7) & ~7;
    if (lane < ncurP - ncur) { pp[ncur + lane] = 0; wp[ncur + lane] = 0.f; }

    base = 0;
    for (int c0 = 512; c0 < K2; c0 += 32) {
        float m = mask[(long long)row * K2 + c0 + lane];
        unsigned bal = __ballot_sync(0xffffffffu, m != 0.f);
        int pre = __popc(bal & ((1u << lane) - 1u));
        if (m != 0.f) {
            pp[ncurP + base + pre] = (unsigned)(c0 + lane - 512) * KT_STRIDE_B;
            wp[ncurP + base + pre] = w_rnn[(long long)row * K2 + c0 + lane];
        }
        base += __popc(bal);
    }
    int nspk = base, nspkP = (nspk + 7) & ~7;
    if (lane < nspkP - nspk) { pp[ncurP + nspk + lane] = 0; wp[ncurP + nspk + lane] = 0.f; }
    if (lane == 0) g_secs[row] = (unsigned)ncurP | ((unsigned)nspkP << 16);
}

// -------- k_proj: projA[t][row][b] = currents(t) . W_cur[row]  (parallel over t)
__global__ void __launch_bounds__(1024, 1)
k_proj() {
    extern __shared__ float s_kT[];   // 512*36 floats
    int tid = threadIdx.x, lane = tid & 31, wid = tid >> 5;
    int u = blockIdx.x;
    int t = u >> 3, rb = u & 7;

    const float4* cur = (const float4*)(g_currents + (long long)t * RR * BSZ);
    #pragma unroll
    for (int j = 0; j < 4; j++) {
        int i = tid + j * 1024;
        int r = i >> 3, b4 = i & 7;
        *(float4*)(s_kT + r * KT_STRIDE + b4 * 4) = __ldg(cur + i);
    }
    __syncthreads();

    const char* ktb = (const char*)s_kT + lane * 4;
    int rowbase = rb * 256 + wid * 8;
    for (int rr = 0; rr < 8; rr++) {
        int row = rowbase + rr;
        int ncurP = g_secs[row] & 0xFFFF;
        const float*    wp = g_wv  + row * ROWSTRIDE;
        const unsigned* pp = g_pidx + row * ROWSTRIDE;
        float a0 = 0.f, a1 = 0.f, a2 = 0.f, a3 = 0.f;
        for (int j = 0; j < ncurP; j += 8) {
            float4 wA = __ldg((const float4*)(wp + j));
            float4 wB = __ldg((const float4*)(wp + j + 4));
            uint4  qA = __ldg((const uint4*)(pp + j));
            uint4  qB = __ldg((const uint4*)(pp + j + 4));
            a0 = fmaf(wA.x, *(const float*)(ktb + qA.x), a0);
            a1 = fmaf(wA.y, *(const float*)(ktb + qA.y), a1);
            a2 = fmaf(wA.z, *(const float*)(ktb + qA.z), a2);
            a3 = fmaf(wA.w, *(const float*)(ktb + qA.w), a3);
            a0 = fmaf(wB.x, *(const float*)(ktb + qB.x), a0);
            a1 = fmaf(wB.y, *(const float*)(ktb + qB.y), a1);
            a2 = fmaf(wB.z, *(const float*)(ktb + qB.z), a2);
            a3 = fmaf(wB.w, *(const float*)(ktb + qB.w), a3);
        }
        g_projA[((long long)t * NROWS + row) * BSZ + lane] = (a0 + a1) + (a2 + a3);
    }
}

// smem float offsets (GEMM CTAs) — spike-only kT
#define SW_OFF   0
#define SI_OFF   (SW_OFF + 16*ROWSTRIDE)
#define KT_OFF   (SI_OFF + 16*ROWSTRIDE)
#define PB_OFF   (KT_OFF + RR*KT_STRIDE)
#define SD_OFF   (PB_OFF + 32*32)
#define SM_OFF   (SD_OFF + 16*33)
#define SS_OFF   (SM_OFF + 4*33)
#define HB_OFF   (SS_OFF + 4*33)
#define BT_OFF   (HB_OFF + 128*9)
#define BN_OFF   (BT_OFF + 16)
#define AL_OFF   (BN_OFF + 16)
#define SEC_OFF  (AL_OFF + 8)
#define SMEM_FLOATS (SEC_OFF + 24)

__device__ __forceinline__ void gemm_sec(
    const float* wp, const unsigned* pp, int cnt,
    const char* ktb, float* dst, int lane)
{
    float a0 = 0.f, a1 = 0.f, a2 = 0.f, a3 = 0.f;
    for (int j = 0; j < cnt; j += 8) {
        float4 wA = *(const float4*)(wp + j);
        uint4  qA = *(const uint4*)(pp + j);
        float4 wB = *(const float4*)(wp + j + 4);
        uint4  qB = *(const uint4*)(pp + j + 4);
        a0 = fmaf(wA.x, *(const float*)(ktb + qA.x), a0);
        a1 = fmaf(wA.y, *(const float*)(ktb + qA.y), a1);
        a2 = fmaf(wA.z, *(const float*)(ktb + qA.z), a2);
        a3 = fmaf(wA.w, *(const float*)(ktb + qA.w), a3);
        a0 = fmaf(wB.x, *(const float*)(ktb + qB.x), a0);
        a1 = fmaf(wB.y, *(const float*)(ktb + qB.y), a1);
        a2 = fmaf(wB.z, *(const float*)(ktb + qB.z), a2);
        a3 = fmaf(wB.w, *(const float*)(ktb + qB.w), a3);
    }
    dst[lane] = (a0 + a1) + (a2 + a3);
}

__global__ void __launch_bounds__(NTH, 1)
k_recurrent(const float* __restrict__ gating,
            const float* __restrict__ b_rnn,
            const float* __restrict__ tau_m,
            const float* __restrict__ tau_n,
            const float* __restrict__ w_ro,
            const float* __restrict__ b_ro,
            const float* __restrict__ tau_m_ro,
            float* __restrict__ out) {
    extern __shared__ float smf[];
    int tid = threadIdx.x, lane = tid & 31, wid = tid >> 5;
    int bid = blockIdx.x;

    if (bid >= GEMM_CTAS) {
        // ======== readout CTAs (20) ========
        float* s_wro = smf;
        float* s_sp  = s_wro + CC * RR;
        for (int i = tid; i < CC * RR; i += NTH) s_wro[i] = w_ro[i];
        __syncthreads();

        int task = (bid - GEMM_CTAS) * 32 + wid;
        bool act = task < BSZ * CC;
        int b_ = act ? task / CC : 0, c_ = act ? task % CC : 0;
        float ao = sigmoidf_(tau_m_ro[c_]), bro = b_ro[c_];
        float m0 = 0.f, sp0 = 0.f;
        int myflag = 128 + (bid - GEMM_CTAS);

        for (int t = 0; t < TT; t++) {
            if (tid < 32) {     // wait: all gemm flags >= t+1
                bool need = true;
                while (need) {
                    bool ok = true;
                    #pragma unroll
                    for (int k = 0; k < 4; k++)
                        if (g_arrive[lane + k * 32] < (unsigned)(t + 1)) ok = false;
                    need = !__all_sync(0xffffffffu, ok);
                    if (need) __nanosleep(20);
                }
            }
            __syncthreads();
            const float* spn = g_spk[(t + 1) & 1];
            for (int e = tid; e < RR * BSZ; e += NTH) {
                int r = e >> 5, b = e & 31;
                s_sp[r * 33 + b] = __ldcg(spn + e);
            }
            __syncthreads();
            if (tid == 0) g_arrive[myflag] = (unsigned)(t + 1);  // buffer consumed
            if (act) {
                float sum = 0.f;
                #pragma unroll
                for (int i = 0; i < RR; i += 32)
                    sum += s_sp[(i + lane) * 33 + b_] * s_wro[c_ * RR + i + lane];
                #pragma unroll
                for (int o = 16; o; o >>= 1) sum += __shfl_xor_sync(0xffffffffu, sum, o);
                m0 = m0 * ao + (1.f - ao) * (sum + bro) - VTH * sp0;
                sp0 = (m0 - VTH) > 0.f ? 1.f : 0.f;
                if (lane == 0) out[(long long)task * TT + t] = m0;
            }
            __syncthreads();
        }
        return;
    }

    // ======== GEMM CTAs (128): 16 rows (4 neurons) x 32 batches ========
    float*    s_w    = smf + SW_OFF;
    unsigned* s_pidx = (unsigned*)(smf + SI_OFF);
    float*    s_kT   = smf + KT_OFF;             // spike half only [512][36]
    float*    s_pB   = smf + PB_OFF;
    float*    s_d    = smf + SD_OFF;
    float*    s_mem  = smf + SM_OFF;
    float*    s_spk  = smf + SS_OFF;
    float*    s_hist = smf + HB_OFF;
    float*    s_beta = smf + BT_OFF;
    float*    s_brnn = smf + BN_OFF;
    float*    s_alph = smf + AL_OFF;
    unsigned* s_secs = (unsigned*)(smf + SEC_OFF);

    int row0 = bid * 16, n0 = bid * 4;

    for (int i = tid; i < 16 * ROWSTRIDE; i += NTH) {
        s_w[i]    = g_wv  [row0 * ROWSTRIDE + i];
        s_pidx[i] = g_pidx[row0 * ROWSTRIDE + i];
    }
    if (tid < 16) {
        s_secs[tid] = g_secs[row0 + tid];
        s_beta[tid] = sigmoidf_(tau_n[(n0 + (tid >> 2)) * BR + (tid & 3)]);
        s_brnn[tid] = b_rnn[row0 + tid];
    }
    if (tid < 4) s_alph[tid] = sigmoidf_(tau_m[n0 + tid]);
    for (int i = tid; i < 16 * 33; i += NTH) s_d[i] = 0.f;
    if (tid < 4 * 33) { s_mem[tid] = 0.f; s_spk[tid] = 0.f; }
    __syncthreads();

    const char* ktb = (const char*)s_kT + lane * 4;

    // hoisted spike-fill addressing (4 float4 per thread)
    int foff_s[4];
    #pragma unroll
    for (int j = 0; j < 4; j++) {
        int i = tid + j * 1024;
        int r = i >> 3, b4 = i & 7;
        foff_s[j] = r * KT_STRIDE + b4 * 4;
    }

    for (int t = 0; t < TT; t++) {
        // prefetch projA(t) + gating for phase3 (wid<4: neuron=wid, batch=lane)
        float pj0 = 0.f, pj1 = 0.f, pj2 = 0.f, pj3 = 0.f, gpre = 0.f;
        if (wid < 4) {
            long long pb = ((long long)t * NROWS + row0 + wid * 4) * BSZ + lane;
            pj0 = __ldg(&g_projA[pb]);
            pj1 = __ldg(&g_projA[pb + BSZ]);
            pj2 = __ldg(&g_projA[pb + 2 * BSZ]);
            pj3 = __ldg(&g_projA[pb + 3 * BSZ]);
            gpre = __ldg(&gating[((long long)lane * TT + t) * RR + n0 + wid]);
        }

        // (A) poll: gemm flags >= t ; readout flags >= t-1 (indices >=148 ignored)
        if (tid < 32 && t > 0) {
            unsigned tgG = (unsigned)t;
            unsigned tgR = (unsigned)(t - 1);
            bool need = true;
            while (need) {
                bool ok = true;
                #pragma unroll
                for (int k = 0; k < 5; k++) {
                    int i = lane + k * 32;
                    unsigned v = (i < 148) ? g_arrive[i] : 0xFFFFFFFFu;
                    if (v < (i < 128 ? tgG : tgR)) ok = false;
                }
                need = !__all_sync(0xffffffffu, ok);
                if (need) __nanosleep(20);
            }
        }
        __syncthreads();

        // (B) fill spike half: spk(t-1)
        {
            const float4* sp = (const float4*)(g_spk[t & 1]);
            #pragma unroll
            for (int j = 0; j < 4; j++)
                *(float4*)(s_kT + foff_s[j]) = __ldcg(sp + tid + j * 1024);
        }
        __syncthreads();

        // (C) spike GEMM -> s_pB (warp = half row)
        {
            int row = wid >> 1, half = wid & 1;
            unsigned sec = s_secs[row];
            int ncurP = sec & 0xFFFF, nspkP = sec >> 16;
            int h0 = (nspkP >> 4) << 3;
            int beg = ncurP + (half ? h0 : 0);
            int cnt = half ? (nspkP - h0) : h0;
            gemm_sec(s_w + row * ROWSTRIDE + beg, s_pidx + row * ROWSTRIDE + beg,
                     cnt, ktb, s_pB + (half * 16 + row) * 32, lane);
        }
        __syncthreads();

        // (D) warps0-3: phase3 + publish
        if (wid < 4) {
            int nl = wid, b = lane;
            float g = gpre;
            float lin = 0.f;
            #pragma unroll
            for (int br = 0; br < BR; br++) {
                int row = nl * 4 + br;
                float pj = br == 0 ? pj0 : br == 1 ? pj1 : br == 2 ? pj2 : pj3;
                float proj = pj + s_pB[row * 32 + b] + s_pB[(16 + row) * 32 + b]
                           + s_brnn[row];
                float beta = s_beta[row];
                float dold = s_d[row * 33 + b];
                float dnew = beta * dold + (1.f - beta) * proj;
                lin += dnew;
                s_d[row * 33 + b] = g * dnew + (1.f - g) * dold;
            }
            float alpha = s_alph[nl];
            float mold = s_mem[nl * 33 + b];
            float sold = s_spk[nl * 33 + b];
            float mnew = mold * alpha + (1.f - alpha) * lin - VTH * sold;
            float snew = (mnew - VTH) > 0.f ? 1.f : 0.f;
            float mg = g * mnew + (1.f - g) * mold;
            float sg = g * snew + (1.f - g) * sold;
            s_mem[nl * 33 + b] = mg;
            s_spk[nl * 33 + b] = sg;
            g_spk[(t + 1) & 1][(n0 + nl) * BSZ + b] = sg;
            s_hist[(nl * 32 + b) * 9 + (t & 7)] = sg;
            __threadfence();
            asm volatile("bar.sync 1, 128;" ::: "memory");
            if (tid == 0) g_arrive[bid] = (unsigned)(t + 1);
            // history dump (after flag; own lane's data only)
            if ((t & 7) == 7) {
                const float* h = s_hist + (nl * 32 + b) * 9;
                float4 v0 = make_float4(h[0], h[1], h[2], h[3]);
                float4 v1 = make_float4(h[4], h[5], h[6], h[7]);
                long long base = OUT0 + ((long long)b * RR + (n0 + nl)) * TT + (t - 7);
                *(float4*)(out + base) = v0;
                *(float4*)(out + base + 4) = v1;
            }
        }
        // no trailing sync: next (A)'s syncthreads covers all hazards
    }
}

extern "C" void kernel_launch(void* const* d_in, const int* in_sizes, int n_in,
                              void* d_out, int out_size) {
    const float* inp      = (const float*)d_in[0];
    const float* gating   = (const float*)d_in[1];
    const float* w_in     = (const float*)d_in[2];
    const float* b_in     = (const float*)d_in[3];
    const float* w_rnn    = (const float*)d_in[4];
    const float* b_rnn    = (const float*)d_in[5];
    const float* tau_m    = (const float*)d_in[6];
    const float* tau_n    = (const float*)d_in[7];
    const float* w_ro     = (const float*)d_in[8];
    const float* b_ro     = (const float*)d_in[9];
    const float* tau_m_ro = (const float*)d_in[10];
    const float* mask     = (const float*)d_in[11];
    float* out = (float*)d_out;

    int smem_rec = SMEM_FLOATS * 4 + 256;        // ~121 KB (readout path needs ~88 KB)
    cudaFuncSetAttribute(k_recurrent,
                         cudaFuncAttributeMaxDynamicSharedMemorySize, smem_rec);
    int smem_proj = RR * KT_STRIDE * 4 + 256;    // ~74 KB
    cudaFuncSetAttribute(k_proj,
                         cudaFuncAttributeMaxDynamicSharedMemorySize, smem_proj);

    k_init<<<64, 256>>>();

    long long total_rows = (long long)BSZ * TT * RR;
    int gridA = (int)((total_rows + 7) / 8);
    k_currents<<<gridA, 256>>>(inp, w_in, b_in);

    k_prep<<<NROWS / 8, 256>>>(w_rnn, mask);

    k_proj<<<TT * 8, 1024, smem_proj>>>();

    k_recurrent<<<NCTA_TOTAL, NTH, smem_rec>>>(gating, b_rnn, tau_m, tau_n,
                                               w_ro, b_ro, tau_m_ro, out);
}

// round 12
// speedup vs baseline: 1.2963x; 1.2963x over previous
#include <cuda_runtime.h>
#include <cuda_bf16.h>

#define BSZ 32
#define TT  200
#define RR  512
#define FF  128
#define BR  4
#define CC  10
#define K2  1024
#define NROWS 2048
#define VTH 0.5f

#define NCTA_TOTAL 148
#define GEMM_CTAS  128
#define NTH 1024

#define KT_STRIDE 36
#define KT_STRIDE_B 144
#define ROWSTRIDE 272     // cur section + spk section, each padded to 8
#define OUT0 (BSZ*CC*TT)
#define SLOT (RR*BSZ)     // 16384 floats per ring slot

// -------- device scratch --------
__device__ float    g_currents[TT * RR * BSZ];     // [T][R][B]
__device__ float    g_ring[4][SLOT];               // epoch-encoded spikes, 4-deep
__device__ unsigned g_pidx[NROWS * ROWSTRIDE];     // absolute byte offsets into kT
__device__ float    g_wv [NROWS * ROWSTRIDE];
__device__ unsigned g_secs[NROWS];                 // ncurP | nspkP<<16
__device__ volatile unsigned g_ro[32];             // readout staged-step+1 (20 used)

__device__ __forceinline__ float sigmoidf_(float x) { return 1.f / (1.f + __expf(-x)); }

__device__ __forceinline__ float4 ldcg4(const float4* p) {
    float4 v;
    asm volatile("ld.global.cg.v4.f32 {%0,%1,%2,%3}, [%4];"
                 : "=f"(v.x), "=f"(v.y), "=f"(v.z), "=f"(v.w) : "l"(p));
    return v;
}

__global__ void k_init() {
    int tid = blockIdx.x * blockDim.x + threadIdx.x;
    // ring: slot 3 holds S(-1)=0 with epoch 1; others 0
    for (int i = tid; i < 4 * SLOT; i += gridDim.x * blockDim.x)
        ((float*)g_ring)[i] = (i >= 3 * SLOT) ? 1.0f : 0.0f;
    if (tid < 32) g_ro[tid] = 0;
}

__global__ void k_currents(const float* __restrict__ inp,
                           const float* __restrict__ w_in,
                           const float* __restrict__ b_in) {
    __shared__ float sw[FF];
    int tid = threadIdx.x;
    if (tid < FF) sw[tid] = w_in[tid];
    __syncthreads();
    int lane = tid & 31, wid = tid >> 5;
    long long rid = (long long)blockIdx.x * 8 + wid;
    if (rid >= (long long)BSZ * TT * RR) return;
    const float4* p = (const float4*)inp + rid * (FF / 4);
    float4 v = p[lane];
    float4 w = ((const float4*)sw)[lane];
    float s = v.x * w.x + v.y * w.y + v.z * w.z + v.w * w.w;
    #pragma unroll
    for (int o = 16; o; o >>= 1) s += __shfl_xor_sync(0xffffffffu, s, o);
    if (lane == 0) {
        int r = (int)(rid % RR);
        long long bt = rid / RR;
        int t = (int)(bt % TT);
        int b = (int)(bt / TT);
        g_currents[((long long)t * RR + r) * BSZ + b] = s + b_in[0];
    }
}

// compact rows: cur section (k<512) then spk section (k>=512); absolute kT byte offsets
__global__ void k_prep(const float* __restrict__ w_rnn,
                       const float* __restrict__ mask) {
    int row = blockIdx.x * 8 + (threadIdx.x >> 5);
    int lane = threadIdx.x & 31;
    if (row >= NROWS) return;
    unsigned* pp = g_pidx + row * ROWSTRIDE;
    float*    wp = g_wv  + row * ROWSTRIDE;

    int base = 0;
    for (int c0 = 0; c0 < 512; c0 += 32) {
        float m = mask[(long long)row * K2 + c0 + lane];
        unsigned bal = __ballot_sync(0xffffffffu, m != 0.f);
        int pre = __popc(bal & ((1u << lane) - 1u));
        if (m != 0.f) {
            pp[base + pre] = (unsigned)(c0 + lane) * KT_STRIDE_B;
            wp[base + pre] = w_rnn[(long long)row * K2 + c0 + lane];
        }
        base += __popc(bal);
    }
    int ncur = base, ncurP = (ncur + 7) & ~7;
    if (lane < ncurP - ncur) { pp[ncur + lane] = 0; wp[ncur + lane] = 0.f; }

    base = 0;
    for (int c0 = 512; c0 < K2; c0 += 32) {
        float m = mask[(long long)row * K2 + c0 + lane];
        unsigned bal = __ballot_sync(0xffffffffu, m != 0.f);
        int pre = __popc(bal & ((1u << lane) - 1u));
        if (m != 0.f) {
            pp[ncurP + base + pre] = (unsigned)(c0 + lane) * KT_STRIDE_B;
            wp[ncurP + base + pre] = w_rnn[(long long)row * K2 + c0 + lane];
        }
        base += __popc(bal);
    }
    int nspk = base, nspkP = (nspk + 7) & ~7;
    if (lane < nspkP - nspk) { pp[ncurP + nspk + lane] = 0; wp[ncurP + nspk + lane] = 0.f; }
    if (lane == 0) g_secs[row] = (unsigned)ncurP | ((unsigned)nspkP << 16);
}

// smem float offsets (GEMM CTAs) — full kT [1024][36]
#define SW_OFF   0
#define SI_OFF   (SW_OFF + 16*ROWSTRIDE)
#define KT_OFF   (SI_OFF + 16*ROWSTRIDE)
#define PA_OFF   (KT_OFF + K2*KT_STRIDE)
#define PB_OFF   (PA_OFF + 32*32)
#define SD_OFF   (PB_OFF + 32*32)
#define SM_OFF   (SD_OFF + 16*33)
#define SS_OFF   (SM_OFF + 4*33)
#define HB_OFF   (SS_OFF + 4*33)
#define BT_OFF   (HB_OFF + 128*9)
#define BN_OFF   (BT_OFF + 16)
#define AL_OFF   (BN_OFF + 16)
#define SEC_OFF  (AL_OFF + 8)
#define SMEM_FLOATS (SEC_OFF + 24)

__device__ __forceinline__ void gemm_sec(
    const float* wp, const unsigned* pp, int cnt,
    const char* ktb, float* dst, int lane)
{
    float a0 = 0.f, a1 = 0.f, a2 = 0.f, a3 = 0.f;
    for (int j = 0; j < cnt; j += 8) {
        float4 wA = *(const float4*)(wp + j);
        uint4  qA = *(const uint4*)(pp + j);
        float4 wB = *(const float4*)(wp + j + 4);
        uint4  qB = *(const uint4*)(pp + j + 4);
        a0 = fmaf(wA.x, *(const float*)(ktb + qA.x), a0);
        a1 = fmaf(wA.y, *(const float*)(ktb + qA.y), a1);
        a2 = fmaf(wA.z, *(const float*)(ktb + qA.z), a2);
        a3 = fmaf(wA.w, *(const float*)(ktb + qA.w), a3);
        a0 = fmaf(wB.x, *(const float*)(ktb + qB.x), a0);
        a1 = fmaf(wB.y, *(const float*)(ktb + qB.y), a1);
        a2 = fmaf(wB.z, *(const float*)(ktb + qB.z), a2);
        a3 = fmaf(wB.w, *(const float*)(ktb + qB.w), a3);
    }
    dst[lane] = (a0 + a1) + (a2 + a3);
}

__global__ void __launch_bounds__(NTH, 1)
k_recurrent(const float* __restrict__ gating,
            const float* __restrict__ b_rnn,
            const float* __restrict__ tau_m,
            const float* __restrict__ tau_n,
            const float* __restrict__ w_ro,
            const float* __restrict__ b_ro,
            const float* __restrict__ tau_m_ro,
            float* __restrict__ out) {
    extern __shared__ float smf[];
    int tid = threadIdx.x, lane = tid & 31, wid = tid >> 5;
    int bid = blockIdx.x;

    if (bid >= GEMM_CTAS) {
        // ======== readout CTAs (20): epoch-poll ring, stage, dot ========
        float* s_wro = smf;                 // 10*512
        float* s_sp  = s_wro + CC * RR;     // 512*33
        for (int i = tid; i < CC * RR; i += NTH) s_wro[i] = w_ro[i];
        __syncthreads();

        int task = (bid - GEMM_CTAS) * 32 + wid;
        bool act = task < BSZ * CC;
        int b_ = act ? task / CC : 0, c_ = act ? task % CC : 0;
        float ao = sigmoidf_(tau_m_ro[c_]), bro = b_ro[c_];
        float m0 = 0.f, sp0 = 0.f;
        int myidx = bid - GEMM_CTAS;

        for (int t = 0; t < TT; t++) {
            // poll-stage S(t) from ring slot t&3 (expect epoch >= t+2)
            const float4* slot4 = (const float4*)(g_ring[t & 3]);
            float thr = (float)(t + 2);
            float4 v0, v1, v2, v3;
            for (;;) {
                v0 = ldcg4(slot4 + tid);
                v1 = ldcg4(slot4 + tid + 1024);
                v2 = ldcg4(slot4 + tid + 2048);
                v3 = ldcg4(slot4 + tid + 3072);
                bool ok = v0.x >= thr && v0.y >= thr && v0.z >= thr && v0.w >= thr
                       && v1.x >= thr && v1.y >= thr && v1.z >= thr && v1.w >= thr
                       && v2.x >= thr && v2.y >= thr && v2.z >= thr && v2.w >= thr
                       && v3.x >= thr && v3.y >= thr && v3.z >= thr && v3.w >= thr;
                if (ok) break;
                __nanosleep(40);
            }
            {
                int i0 = tid, r, b4;
                r = i0 >> 3; b4 = (i0 & 7) * 4;
                s_sp[r * 33 + b4] = v0.x - thr; s_sp[r * 33 + b4 + 1] = v0.y - thr;
                s_sp[r * 33 + b4 + 2] = v0.z - thr; s_sp[r * 33 + b4 + 3] = v0.w - thr;
                i0 = tid + 1024; r = i0 >> 3; b4 = (i0 & 7) * 4;
                s_sp[r * 33 + b4] = v1.x - thr; s_sp[r * 33 + b4 + 1] = v1.y - thr;
                s_sp[r * 33 + b4 + 2] = v1.z - thr; s_sp[r * 33 + b4 + 3] = v1.w - thr;
                i0 = tid + 2048; r = i0 >> 3; b4 = (i0 & 7) * 4;
                s_sp[r * 33 + b4] = v2.x - thr; s_sp[r * 33 + b4 + 1] = v2.y - thr;
                s_sp[r * 33 + b4 + 2] = v2.z - thr; s_sp[r * 33 + b4 + 3] = v2.w - thr;
                i0 = tid + 3072; r = i0 >> 3; b4 = (i0 & 7) * 4;
                s_sp[r * 33 + b4] = v3.x - thr; s_sp[r * 33 + b4 + 1] = v3.y - thr;
                s_sp[r * 33 + b4 + 2] = v3.z - thr; s_sp[r * 33 + b4 + 3] = v3.w - thr;
            }
            __syncthreads();
            if (tid == 0) g_ro[myidx] = (unsigned)(t + 1);   // staged S(t)
            if (act) {
                float sum = 0.f;
                #pragma unroll
                for (int i = 0; i < RR; i += 32)
                    sum += s_sp[(i + lane) * 33 + b_] * s_wro[c_ * RR + i + lane];
                #pragma unroll
                for (int o = 16; o; o >>= 1) sum += __shfl_xor_sync(0xffffffffu, sum, o);
                m0 = m0 * ao + (1.f - ao) * (sum + bro) - VTH * sp0;
                sp0 = (m0 - VTH) > 0.f ? 1.f : 0.f;
                if (lane == 0) out[(long long)task * TT + t] = m0;
            }
            __syncthreads();
        }
        return;
    }

    // ======== GEMM CTAs (128): 16 rows (4 neurons) x 32 batches ========
    float*    s_w    = smf + SW_OFF;
    unsigned* s_pidx = (unsigned*)(smf + SI_OFF);
    float*    s_kT   = smf + KT_OFF;
    float*    s_pA   = smf + PA_OFF;
    float*    s_pB   = smf + PB_OFF;
    float*    s_d    = smf + SD_OFF;
    float*    s_mem  = smf + SM_OFF;
    float*    s_spk  = smf + SS_OFF;
    float*    s_hist = smf + HB_OFF;
    float*    s_beta = smf + BT_OFF;
    float*    s_brnn = smf + BN_OFF;
    float*    s_alph = smf + AL_OFF;
    unsigned* s_secs = (unsigned*)(smf + SEC_OFF);

    int row0 = bid * 16, n0 = bid * 4;

    for (int i = tid; i < 16 * ROWSTRIDE; i += NTH) {
        s_w[i]    = g_wv  [row0 * ROWSTRIDE + i];
        s_pidx[i] = g_pidx[row0 * ROWSTRIDE + i];
    }
    if (tid < 16) {
        s_secs[tid] = g_secs[row0 + tid];
        s_beta[tid] = sigmoidf_(tau_n[(n0 + (tid >> 2)) * BR + (tid & 3)]);
        s_brnn[tid] = b_rnn[row0 + tid];
    }
    if (tid < 4) s_alph[tid] = sigmoidf_(tau_m[n0 + tid]);
    for (int i = tid; i < 16 * 33; i += NTH) s_d[i] = 0.f;
    if (tid < 4 * 33) { s_mem[tid] = 0.f; s_spk[tid] = 0.f; }
    __syncthreads();

    const char* ktb = (const char*)s_kT + lane * 4;

    // hoisted fill addressing (float4 index i = tid + j*1024)
    int foff_c[4], foff_s[4];
    #pragma unroll
    for (int j = 0; j < 4; j++) {
        int i = tid + j * 1024;
        int r = i >> 3, b4 = i & 7;
        foff_c[j] = r * KT_STRIDE + b4 * 4;
        foff_s[j] = (RR + r) * KT_STRIDE + b4 * 4;
    }

    // prologue: fill currents(0), currents-GEMM(0) -> s_pA
    {
        const float4* cur = (const float4*)g_currents;
        #pragma unroll
        for (int j = 0; j < 4; j++)
            *(float4*)(s_kT + foff_c[j]) = __ldg(cur + tid + j * 1024);
    }
    __syncthreads();
    {
        int row = wid >> 1, half = wid & 1;
        int ncurP = s_secs[row] & 0xFFFF;
        int h0 = (ncurP >> 4) << 3;
        int beg = half ? h0 : 0;
        int cnt = half ? (ncurP - h0) : h0;
        gemm_sec(s_w + row * ROWSTRIDE + beg, s_pidx + row * ROWSTRIDE + beg,
                 cnt, ktb, s_pA + (half * 16 + row) * 32, lane);
    }
    __syncthreads();

    for (int t = 0; t < TT; t++) {
        // gating prefetch for phase3 (wid<4: neuron=wid, batch=lane)
        float gpre = 0.f;
        if (wid < 4)
            gpre = __ldg(&gating[((long long)lane * TT + t) * RR + n0 + wid]);

        // (B) poll-fill S(t-1) from ring slot (t-1)&3 (epoch >= t+1); decode into kT
        {
            const float4* slot4 = (const float4*)(g_ring[(t + 3) & 3]);
            float thr = (float)(t + 1);
            float4 v0, v1, v2, v3;
            for (;;) {
                v0 = ldcg4(slot4 + tid);
                v1 = ldcg4(slot4 + tid + 1024);
                v2 = ldcg4(slot4 + tid + 2048);
                v3 = ldcg4(slot4 + tid + 3072);
                bool ok = v0.x >= thr && v0.y >= thr && v0.z >= thr && v0.w >= thr
                       && v1.x >= thr && v1.y >= thr && v1.z >= thr && v1.w >= thr
                       && v2.x >= thr && v2.y >= thr && v2.z >= thr && v2.w >= thr
                       && v3.x >= thr && v3.y >= thr && v3.z >= thr && v3.w >= thr;
                if (ok) break;
                __nanosleep(40);
            }
            v0.x -= thr; v0.y -= thr; v0.z -= thr; v0.w -= thr;
            v1.x -= thr; v1.y -= thr; v1.z -= thr; v1.w -= thr;
            v2.x -= thr; v2.y -= thr; v2.z -= thr; v2.w -= thr;
            v3.x -= thr; v3.y -= thr; v3.z -= thr; v3.w -= thr;
            *(float4*)(s_kT + foff_s[0]) = v0;
            *(float4*)(s_kT + foff_s[1]) = v1;
            *(float4*)(s_kT + foff_s[2]) = v2;
            *(float4*)(s_kT + foff_s[3]) = v3;
        }
        __syncthreads();

        // (C) spike GEMM -> s_pB (warp = half row)
        {
            int row = wid >> 1, half = wid & 1;
            unsigned sec = s_secs[row];
            int ncurP = sec & 0xFFFF, nspkP = sec >> 16;
            int h0 = (nspkP >> 4) << 3;
            int beg = ncurP + (half ? h0 : 0);
            int cnt = half ? (nspkP - h0) : h0;
            gemm_sec(s_w + row * ROWSTRIDE + beg, s_pidx + row * ROWSTRIDE + beg,
                     cnt, ktb, s_pB + (half * 16 + row) * 32, lane);
        }
        __syncthreads();

        // (D) wid<4: phase3, publish S(t) with epoch t+2 | wid>=4: fill cur(t+1)
        if (wid < 4) {
            int nl = wid, b = lane;
            float g = gpre;
            float lin = 0.f;
            #pragma unroll
            for (int br = 0; br < BR; br++) {
                int row = nl * 4 + br;
                float proj = s_pA[row * 32 + b] + s_pA[(16 + row) * 32 + b]
                           + s_pB[row * 32 + b] + s_pB[(16 + row) * 32 + b]
                           + s_brnn[row];
                float beta = s_beta[row];
                float dold = s_d[row * 33 + b];
                float dnew = beta * dold + (1.f - beta) * proj;
                lin += dnew;
                s_d[row * 33 + b] = g * dnew + (1.f - g) * dold;
            }
            float alpha = s_alph[nl];
            float mold = s_mem[nl * 33 + b];
            float sold = s_spk[nl * 33 + b];
            float mnew = mold * alpha + (1.f - alpha) * lin - VTH * sold;
            float snew = (mnew - VTH) > 0.f ? 1.f : 0.f;
            float mg = g * mnew + (1.f - g) * mold;
            float sg = g * snew + (1.f - g) * sold;
            // publish FIRST (data is the flag; epoch makes it unambiguous)
            __stcg(&g_ring[t & 3][(n0 + nl) * BSZ + b], sg + (float)(t + 2));
            s_mem[nl * 33 + b] = mg;
            s_spk[nl * 33 + b] = sg;
            s_hist[(nl * 32 + b) * 9 + (t & 7)] = sg;
            if ((t & 7) == 7) {   // own-lane history dump, coalesced per warp
                const float* h = s_hist + (nl * 32 + b) * 9;
                float4 w0 = make_float4(h[0], h[1], h[2], h[3]);
                float4 w1 = make_float4(h[4], h[5], h[6], h[7]);
                long long base = OUT0 + ((long long)b * RR + (n0 + nl)) * TT + (t - 7);
                *(float4*)(out + base) = w0;
                *(float4*)(out + base + 4) = w1;
            }
        } else if (t + 1 < TT) {
            const float4* curN = (const float4*)g_currents + (long long)(t + 1) * 4096;
            for (int i = tid - 128; i < 4096; i += NTH - 128) {
                int r = i >> 3, b4 = i & 7;
                *(float4*)(s_kT + r * KT_STRIDE + b4 * 4) = __ldg(curN + i);
            }
        }
        __syncthreads();

        // (E) currents GEMM(t+1) -> s_pA (overlaps other CTAs' skew);
        //     wid27 also verifies readout lag (3 steps slack, rarely blocks)
        if (wid == 27 && t >= 2) {
            if (lane < 20) {
                while (g_ro[lane] < (unsigned)(t - 2)) __nanosleep(40);
            }
            __syncwarp();
        }
        if (t + 1 < TT) {
            int row = wid >> 1, half = wid & 1;
            int ncurP = s_secs[row] & 0xFFFF;
            int h0 = (ncurP >> 4) << 3;
            int beg = half ? h0 : 0;
            int cnt = half ? (ncurP - h0) : h0;
            gemm_sec(s_w + row * ROWSTRIDE + beg, s_pidx + row * ROWSTRIDE + beg,
                     cnt, ktb, s_pA + (half * 16 + row) * 32, lane);
        }
        // no trailing sync: (B)'s poll + sync covers next-iteration hazards
    }
}

extern "C" void kernel_launch(void* const* d_in, const int* in_sizes, int n_in,
                              void* d_out, int out_size) {
    const float* inp      = (const float*)d_in[0];
    const float* gating   = (const float*)d_in[1];
    const float* w_in     = (const float*)d_in[2];
    const float* b_in     = (const float*)d_in[3];
    const float* w_rnn    = (const float*)d_in[4];
    const float* b_rnn    = (const float*)d_in[5];
    const float* tau_m    = (const float*)d_in[6];
    const float* tau_n    = (const float*)d_in[7];
    const float* w_ro     = (const float*)d_in[8];
    const float* b_ro     = (const float*)d_in[9];
    const float* tau_m_ro = (const float*)d_in[10];
    const float* mask     = (const float*)d_in[11];
    float* out = (float*)d_out;

    int smem_rec = SMEM_FLOATS * 4 + 256;   // ~199 KB (readout path uses ~88 KB)
    cudaFuncSetAttribute(k_recurrent,
                         cudaFuncAttributeMaxDynamicSharedMemorySize, smem_rec);

    k_init<<<64, 256>>>();

    long long total_rows = (long long)BSZ * TT * RR;
    int gridA = (int)((total_rows + 7) / 8);
    k_currents<<<gridA, 256>>>(inp, w_in, b_in);

    k_prep<<<NROWS / 8, 256>>>(w_rnn, mask);

    k_recurrent<<<NCTA_TOTAL, NTH, smem_rec>>>(gating, b_rnn, tau_m, tau_n,
                                               w_ro, b_ro, tau_m_ro, out);
}

// round 14
// speedup vs baseline: 1.3628x; 1.0513x over previous
#include <cuda_runtime.h>
#include <cuda_bf16.h>

#define BSZ 32
#define TT  200
#define RR  512
#define FF  128
#define BR  4
#define CC  10
#define K2  1024
#define NROWS 2048
#define VTH 0.5f

#define NCTA_TOTAL 148
#define GEMM_CTAS  128
#define NTH 1024

#define KT_STRIDE 36
#define ROWSTRIDE 272     // cur section + spk section, each padded to 8
#define OUT0 (BSZ*CC*TT)
#define SLOT (RR*BSZ)     // 16384 floats per ring slot

// -------- device scratch --------
__device__ float          g_currents[TT * RR * BSZ];   // [T][R][B]
__device__ float          g_ring[4][SLOT];             // epoch-encoded spikes
__device__ unsigned short g_pidx16[NROWS * ROWSTRIDE]; // k*36 (fits u16)
__device__ float          g_wv [NROWS * ROWSTRIDE];
__device__ unsigned       g_secs[NROWS];               // ncurP | nspkP<<16
__device__ volatile unsigned g_ro[32];                 // readout staged-step+1

__device__ __forceinline__ float sigmoidf_(float x) { return 1.f / (1.f + __expf(-x)); }

__device__ __forceinline__ float4 ldcg4(const float4* p) {
    float4 v;
    asm volatile("ld.global.cg.v4.f32 {%0,%1,%2,%3}, [%4];"
                 : "=f"(v.x), "=f"(v.y), "=f"(v.z), "=f"(v.w) : "l"(p));
    return v;
}

__global__ void k_init() {
    int tid = blockIdx.x * blockDim.x + threadIdx.x;
    for (int i = tid; i < 4 * SLOT; i += gridDim.x * blockDim.x)
        ((float*)g_ring)[i] = (i >= 3 * SLOT) ? 1.0f : 0.0f;  // slot3: S(-1)=0,epoch1
    if (tid < 32) g_ro[tid] = 0;
}

__global__ void k_currents(const float* __restrict__ inp,
                           const float* __restrict__ w_in,
                           const float* __restrict__ b_in) {
    __shared__ float sw[FF];
    int tid = threadIdx.x;
    if (tid < FF) sw[tid] = w_in[tid];
    __syncthreads();
    int lane = tid & 31, wid = tid >> 5;
    long long rid = (long long)blockIdx.x * 8 + wid;
    if (rid >= (long long)BSZ * TT * RR) return;
    const float4* p = (const float4*)inp + rid * (FF / 4);
    float4 v = p[lane];
    float4 w = ((const float4*)sw)[lane];
    float s = v.x * w.x + v.y * w.y + v.z * w.z + v.w * w.w;
    #pragma unroll
    for (int o = 16; o; o >>= 1) s += __shfl_xor_sync(0xffffffffu, s, o);
    if (lane == 0) {
        int r = (int)(rid % RR);
        long long bt = rid / RR;
        int t = (int)(bt % TT);
        int b = (int)(bt / TT);
        g_currents[((long long)t * RR + r) * BSZ + b] = s + b_in[0];
    }
}

// compact rows: cur section (k<512) then spk section (k>=512); u16 idx = k*36
__global__ void k_prep(const float* __restrict__ w_rnn,
                       const float* __restrict__ mask) {
    int row = blockIdx.x * 8 + (threadIdx.x >> 5);
    int lane = threadIdx.x & 31;
    if (row >= NROWS) return;
    unsigned short* pp = g_pidx16 + row * ROWSTRIDE;
    float*          wp = g_wv    + row * ROWSTRIDE;

    int base = 0;
    for (int c0 = 0; c0 < 512; c0 += 32) {
        float m = mask[(long long)row * K2 + c0 + lane];
        unsigned bal = __ballot_sync(0xffffffffu, m != 0.f);
        int pre = __popc(bal & ((1u << lane) - 1u));
        if (m != 0.f) {
            pp[base + pre] = (unsigned short)((c0 + lane) * KT_STRIDE);
            wp[base + pre] = w_rnn[(long long)row * K2 + c0 + lane];
        }
        base += __popc(bal);
    }
    int ncur = base, ncurP = (ncur + 7) & ~7;
    if (lane < ncurP - ncur) { pp[ncur + lane] = 0; wp[ncur + lane] = 0.f; }

    base = 0;
    for (int c0 = 512; c0 < K2; c0 += 32) {
        float m = mask[(long long)row * K2 + c0 + lane];
        unsigned bal = __ballot_sync(0xffffffffu, m != 0.f);
        int pre = __popc(bal & ((1u << lane) - 1u));
        if (m != 0.f) {
            pp[ncurP + base + pre] = (unsigned short)((c0 + lane) * KT_STRIDE);
            wp[ncurP + base + pre] = w_rnn[(long long)row * K2 + c0 + lane];
        }
        base += __popc(bal);
    }
    int nspk = base, nspkP = (nspk + 7) & ~7;
    if (lane < nspkP - nspk) { pp[ncurP + nspk + lane] = 0; wp[ncurP + nspk + lane] = 0.f; }
    if (lane == 0) g_secs[row] = (unsigned)ncurP | ((unsigned)nspkP << 16);
}

// smem float offsets (GEMM CTAs) — full kT [1024][36]
#define SW_OFF   0
#define SI_OFF   (SW_OFF + 16*ROWSTRIDE)           // u16 idx: 16*272 u16 = 2176 f
#define KT_OFF   (SI_OFF + 8*ROWSTRIDE)
#define PA_OFF   (KT_OFF + K2*KT_STRIDE)
#define PB_OFF   (PA_OFF + 32*32)
#define SD_OFF   (PB_OFF + 32*32)
#define SM_OFF   (SD_OFF + 16*33)
#define SS_OFF   (SM_OFF + 4*33)
#define HB_OFF   (SS_OFF + 4*33)
#define BT_OFF   (HB_OFF + 128*9)
#define BN_OFF   (BT_OFF + 16)
#define AL_OFF   (BN_OFF + 16)
#define SEC_OFF  (AL_OFF + 8)
#define SMEM_FLOATS (SEC_OFF + 24)

// paired sparse GEMM: lane&15 = batch pair, lane>>4 = nnz parity.
// One LDS.64 per lane serves (1 nnz, 2 batches); warp covers 2 nnz/instr.
// sh = (lane & 16) selects even/odd nnz u16 halves and matching weights.
__device__ __forceinline__ void gemm_pair(
    const float* wp, const unsigned short* ip, int cnt,
    const char* ktp, unsigned sh, float* dst, int lane)
{
    float a0 = 0.f, a1 = 0.f, b0 = 0.f, b1 = 0.f;
    for (int j = 0; j < cnt; j += 8) {
        float4 wA = *(const float4*)(wp + j);
        float4 wB = *(const float4*)(wp + j + 4);
        uint4  q  = *(const uint4*)(ip + j);      // 8 x u16 (k*36)
        unsigned o0 = ((q.x >> sh) & 0xFFFFu) * 4u;
        unsigned o1 = ((q.y >> sh) & 0xFFFFu) * 4u;
        unsigned o2 = ((q.z >> sh) & 0xFFFFu) * 4u;
        unsigned o3 = ((q.w >> sh) & 0xFFFFu) * 4u;
        float w0 = sh ? wA.y : wA.x;
        float w1 = sh ? wA.w : wA.z;
        float w2 = sh ? wB.y : wB.x;
        float w3 = sh ? wB.w : wB.z;
        float2 v0 = *(const float2*)(ktp + o0);
        float2 v1 = *(const float2*)(ktp + o1);
        float2 v2 = *(const float2*)(ktp + o2);
        float2 v3 = *(const float2*)(ktp + o3);
        a0 = fmaf(w0, v0.x, a0); a1 = fmaf(w0, v0.y, a1);
        b0 = fmaf(w1, v1.x, b0); b1 = fmaf(w1, v1.y, b1);
        a0 = fmaf(w2, v2.x, a0); a1 = fmaf(w2, v2.y, a1);
        b0 = fmaf(w3, v3.x, b0); b1 = fmaf(w3, v3.y, b1);
    }
    a0 += b0; a1 += b1;
    a0 += __shfl_xor_sync(0xffffffffu, a0, 16);
    a1 += __shfl_xor_sync(0xffffffffu, a1, 16);
    if (lane < 16) *(float2*)(dst + lane * 2) = make_float2(a0, a1);
}

__global__ void __launch_bounds__(NTH, 1)
k_recurrent(const float* __restrict__ gating,
            const float* __restrict__ b_rnn,
            const float* __restrict__ tau_m,
            const float* __restrict__ tau_n,
            const float* __restrict__ w_ro,
            const float* __restrict__ b_ro,
            const float* __restrict__ tau_m_ro,
            float* __restrict__ out) {
    extern __shared__ float smf[];
    int tid = threadIdx.x, lane = tid & 31, wid = tid >> 5;
    int bid = blockIdx.x;

    if (bid >= GEMM_CTAS) {
        // ======== readout CTAs (20): epoch-poll ring, stage, dot ========
        float* s_wro = smf;
        float* s_sp  = s_wro + CC * RR;
        for (int i = tid; i < CC * RR; i += NTH) s_wro[i] = w_ro[i];
        __syncthreads();

        int task = (bid - GEMM_CTAS) * 32 + wid;
        bool act = task < BSZ * CC;
        int b_ = act ? task / CC : 0, c_ = act ? task % CC : 0;
        float ao = sigmoidf_(tau_m_ro[c_]), bro = b_ro[c_];
        float m0 = 0.f, sp0 = 0.f;
        int myidx = bid - GEMM_CTAS;

        for (int t = 0; t < TT; t++) {
            const float4* slot4 = (const float4*)(g_ring[t & 3]);
            float thr = (float)(t + 2);
            float4 v0, v1, v2, v3;
            for (;;) {
                v0 = ldcg4(slot4 + tid);
                v1 = ldcg4(slot4 + tid + 1024);
                v2 = ldcg4(slot4 + tid + 2048);
                v3 = ldcg4(slot4 + tid + 3072);
                bool ok = v0.x >= thr && v0.y >= thr && v0.z >= thr && v0.w >= thr
                       && v1.x >= thr && v1.y >= thr && v1.z >= thr && v1.w >= thr
                       && v2.x >= thr && v2.y >= thr && v2.z >= thr && v2.w >= thr
                       && v3.x >= thr && v3.y >= thr && v3.z >= thr && v3.w >= thr;
                if (ok) break;
                __nanosleep(40);
            }
            {
                int i0 = tid, r, b4;
                r = i0 >> 3; b4 = (i0 & 7) * 4;
                s_sp[r * 33 + b4] = v0.x - thr; s_sp[r * 33 + b4 + 1] = v0.y - thr;
                s_sp[r * 33 + b4 + 2] = v0.z - thr; s_sp[r * 33 + b4 + 3] = v0.w - thr;
                i0 = tid + 1024; r = i0 >> 3; b4 = (i0 & 7) * 4;
                s_sp[r * 33 + b4] = v1.x - thr; s_sp[r * 33 + b4 + 1] = v1.y - thr;
                s_sp[r * 33 + b4 + 2] = v1.z - thr; s_sp[r * 33 + b4 + 3] = v1.w - thr;
                i0 = tid + 2048; r = i0 >> 3; b4 = (i0 & 7) * 4;
                s_sp[r * 33 + b4] = v2.x - thr; s_sp[r * 33 + b4 + 1] = v2.y - thr;
                s_sp[r * 33 + b4 + 2] = v2.z - thr; s_sp[r * 33 + b4 + 3] = v2.w - thr;
                i0 = tid + 3072; r = i0 >> 3; b4 = (i0 & 7) * 4;
                s_sp[r * 33 + b4] = v3.x - thr; s_sp[r * 33 + b4 + 1] = v3.y - thr;
                s_sp[r * 33 + b4 + 2] = v3.z - thr; s_sp[r * 33 + b4 + 3] = v3.w - thr;
            }
            __syncthreads();
            if (tid == 0) g_ro[myidx] = (unsigned)(t + 1);
            if (act) {
                float sum = 0.f;
                #pragma unroll
                for (int i = 0; i < RR; i += 32)
                    sum += s_sp[(i + lane) * 33 + b_] * s_wro[c_ * RR + i + lane];
                #pragma unroll
                for (int o = 16; o; o >>= 1) sum += __shfl_xor_sync(0xffffffffu, sum, o);
                m0 = m0 * ao + (1.f - ao) * (sum + bro) - VTH * sp0;
                sp0 = (m0 - VTH) > 0.f ? 1.f : 0.f;
                if (lane == 0) out[(long long)task * TT + t] = m0;
            }
            __syncthreads();
        }
        return;
    }

    // ======== GEMM CTAs (128): 16 rows (4 neurons) x 32 batches ========
    float*          s_w    = smf + SW_OFF;
    unsigned short* s_idx  = (unsigned short*)(smf + SI_OFF);
    float*          s_kT   = smf + KT_OFF;
    float*          s_pA   = smf + PA_OFF;
    float*          s_pB   = smf + PB_OFF;
    float*          s_d    = smf + SD_OFF;
    float*          s_mem  = smf + SM_OFF;
    float*          s_spk  = smf + SS_OFF;
    float*          s_hist = smf + HB_OFF;
    float*          s_beta = smf + BT_OFF;
    float*          s_brnn = smf + BN_OFF;
    float*          s_alph = smf + AL_OFF;
    unsigned*       s_secs = (unsigned*)(smf + SEC_OFF);

    int row0 = bid * 16, n0 = bid * 4;

    for (int i = tid; i < 16 * ROWSTRIDE; i += NTH)
        s_w[i] = g_wv[row0 * ROWSTRIDE + i];
    for (int i = tid; i < 16 * ROWSTRIDE / 2; i += NTH)
        ((unsigned*)s_idx)[i] = ((const unsigned*)(g_pidx16 + row0 * ROWSTRIDE))[i];
    if (tid < 16) {
        s_secs[tid] = g_secs[row0 + tid];
        s_beta[tid] = sigmoidf_(tau_n[(n0 + (tid >> 2)) * BR + (tid & 3)]);
        s_brnn[tid] = b_rnn[row0 + tid];
    }
    if (tid < 4) s_alph[tid] = sigmoidf_(tau_m[n0 + tid]);
    for (int i = tid; i < 16 * 33; i += NTH) s_d[i] = 0.f;
    if (tid < 4 * 33) { s_mem[tid] = 0.f; s_spk[tid] = 0.f; }
    __syncthreads();

    const char* ktp = (const char*)s_kT + (lane & 15) * 8;  // batch-pair base
    unsigned sh = (unsigned)(lane & 16);                     // 0 or 16

    // hoisted fill addressing (float4 index i = tid + j*1024)
    int foff_c[4], foff_s[4];
    #pragma unroll
    for (int j = 0; j < 4; j++) {
        int i = tid + j * 1024;
        int r = i >> 3, b4 = i & 7;
        foff_c[j] = r * KT_STRIDE + b4 * 4;
        foff_s[j] = (RR + r) * KT_STRIDE + b4 * 4;
    }

    // prologue: fill currents(0), currents-GEMM(0) -> s_pA
    {
        const float4* cur = (const float4*)g_currents;
        #pragma unroll
        for (int j = 0; j < 4; j++)
            *(float4*)(s_kT + foff_c[j]) = __ldg(cur + tid + j * 1024);
    }
    __syncthreads();
    {
        int row = wid >> 1, half = wid & 1;
        int ncurP = s_secs[row] & 0xFFFF;
        int h0 = (ncurP >> 4) << 3;
        int beg = half ? h0 : 0;
        int cnt = half ? (ncurP - h0) : h0;
        gemm_pair(s_w + row * ROWSTRIDE + beg, s_idx + row * ROWSTRIDE + beg,
                  cnt, ktp, sh, s_pA + (half * 16 + row) * 32, lane);
    }
    __syncthreads();

    for (int t = 0; t < TT; t++) {
        float gpre = 0.f;
        if (wid < 4)
            gpre = __ldg(&gating[((long long)lane * TT + t) * RR + n0 + wid]);

        // (B) poll-fill S(t-1) from ring slot (t-1)&3 (epoch >= t+1)
        {
            const float4* slot4 = (const float4*)(g_ring[(t + 3) & 3]);
            float thr = (float)(t + 1);
            float4 v0, v1, v2, v3;
            for (;;) {
                v0 = ldcg4(slot4 + tid);
                v1 = ldcg4(slot4 + tid + 1024);
                v2 = ldcg4(slot4 + tid + 2048);
                v3 = ldcg4(slot4 + tid + 3072);
                bool ok = v0.x >= thr && v0.y >= thr && v0.z >= thr && v0.w >= thr
                       && v1.x >= thr && v1.y >= thr && v1.z >= thr && v1.w >= thr
                       && v2.x >= thr && v2.y >= thr && v2.z >= thr && v2.w >= thr
                       && v3.x >= thr && v3.y >= thr && v3.z >= thr && v3.w >= thr;
                if (ok) break;
                __nanosleep(40);
            }
            v0.x -= thr; v0.y -= thr; v0.z -= thr; v0.w -= thr;
            v1.x -= thr; v1.y -= thr; v1.z -= thr; v1.w -= thr;
            v2.x -= thr; v2.y -= thr; v2.z -= thr; v2.w -= thr;
            v3.x -= thr; v3.y -= thr; v3.z -= thr; v3.w -= thr;
            *(float4*)(s_kT + foff_s[0]) = v0;
            *(float4*)(s_kT + foff_s[1]) = v1;
            *(float4*)(s_kT + foff_s[2]) = v2;
            *(float4*)(s_kT + foff_s[3]) = v3;
        }
        __syncthreads();

        // (C) spike GEMM -> s_pB (paired gathers)
        {
            int row = wid >> 1, half = wid & 1;
            unsigned sec = s_secs[row];
            int ncurP = sec & 0xFFFF, nspkP = sec >> 16;
            int h0 = (nspkP >> 4) << 3;
            int beg = ncurP + (half ? h0 : 0);
            int cnt = half ? (nspkP - h0) : h0;
            gemm_pair(s_w + row * ROWSTRIDE + beg, s_idx + row * ROWSTRIDE + beg,
                      cnt, ktp, sh, s_pB + (half * 16 + row) * 32, lane);
        }
        __syncthreads();

        // (D) wid<4: phase3, publish S(t) epoch t+2 | wid>=4: fill cur(t+1)
        if (wid < 4) {
            int nl = wid, b = lane;
            float g = gpre;
            float lin = 0.f;
            #pragma unroll
            for (int br = 0; br < BR; br++) {
                int row = nl * 4 + br;
                float proj = s_pA[row * 32 + b] + s_pA[(16 + row) * 32 + b]
                           + s_pB[row * 32 + b] + s_pB[(16 + row) * 32 + b]
                           + s_brnn[row];
                float beta = s_beta[row];
                float dold = s_d[row * 33 + b];
                float dnew = beta * dold + (1.f - beta) * proj;
                lin += dnew;
                s_d[row * 33 + b] = g * dnew + (1.f - g) * dold;
            }
            float alpha = s_alph[nl];
            float mold = s_mem[nl * 33 + b];
            float sold = s_spk[nl * 33 + b];
            float mnew = mold * alpha + (1.f - alpha) * lin - VTH * sold;
            float snew = (mnew - VTH) > 0.f ? 1.f : 0.f;
            float mg = g * mnew + (1.f - g) * mold;
            float sg = g * snew + (1.f - g) * sold;
            __stcg(&g_ring[t & 3][(n0 + nl) * BSZ + b], sg + (float)(t + 2));
            s_mem[nl * 33 + b] = mg;
            s_spk[nl * 33 + b] = sg;
            s_hist[(nl * 32 + b) * 9 + (t & 7)] = sg;
            if ((t & 7) == 7) {
                const float* h = s_hist + (nl * 32 + b) * 9;
                float4 w0 = make_float4(h[0], h[1], h[2], h[3]);
                float4 w1 = make_float4(h[4], h[5], h[6], h[7]);
                long long base = OUT0 + ((long long)b * RR + (n0 + nl)) * TT + (t - 7);
                *(float4*)(out + base) = w0;
                *(float4*)(out + base + 4) = w1;
            }
        } else if (t + 1 < TT) {
            const float4* curN = (const float4*)g_currents + (long long)(t + 1) * 4096;
            for (int i = tid - 128; i < 4096; i += NTH - 128) {
                int r = i >> 3, b4 = i & 7;
                *(float4*)(s_kT + r * KT_STRIDE + b4 * 4) = __ldg(curN + i);
            }
        }
        __syncthreads();

        // (E) currents GEMM(t+1) -> s_pA; wid27 lazily guards readout lag
        if (wid == 27 && t >= 2) {
            if (lane < 20) {
                while (g_ro[lane] < (unsigned)(t - 2)) __nanosleep(40);
            }
            __syncwarp();
        }
        if (t + 1 < TT) {
            int row = wid >> 1, half = wid & 1;
            int ncurP = s_secs[row] & 0xFFFF;
            int h0 = (ncurP >> 4) << 3;
            int beg = half ? h0 : 0;
            int cnt = half ? (ncurP - h0) : h0;
            gemm_pair(s_w + row * ROWSTRIDE + beg, s_idx + row * ROWSTRIDE + beg,
                      cnt, ktp, sh, s_pA + (half * 16 + row) * 32, lane);
        }
        // no trailing sync: (B)'s poll + sync covers next-iteration hazards
    }
}

extern "C" void kernel_launch(void* const* d_in, const int* in_sizes, int n_in,
                              void* d_out, int out_size) {
    const float* inp      = (const float*)d_in[0];
    const float* gating   = (const float*)d_in[1];
    const float* w_in     = (const float*)d_in[2];
    const float* b_in     = (const float*)d_in[3];
    const float* w_rnn    = (const float*)d_in[4];
    const float* b_rnn    = (const float*)d_in[5];
    const float* tau_m    = (const float*)d_in[6];
    const float* tau_n    = (const float*)d_in[7];
    const float* w_ro     = (const float*)d_in[8];
    const float* b_ro     = (const float*)d_in[9];
    const float* tau_m_ro = (const float*)d_in[10];
    const float* mask     = (const float*)d_in[11];
    float* out = (float*)d_out;

    int smem_rec = SMEM_FLOATS * 4 + 256;   // ~190 KB (readout path uses ~88 KB)
    cudaFuncSetAttribute(k_recurrent,
                         cudaFuncAttributeMaxDynamicSharedMemorySize, smem_rec);

    k_init<<<64, 256>>>();

    long long total_rows = (long long)BSZ * TT * RR;
    int gridA = (int)((total_rows + 7) / 8);
    k_currents<<<gridA, 256>>>(inp, w_in, b_in);

    k_prep<<<NROWS / 8, 256>>>(w_rnn, mask);

    k_recurrent<<<NCTA_TOTAL, NTH, smem_rec>>>(gating, b_rnn, tau_m, tau_n,
                                               w_ro, b_ro, tau_m_ro, out);
}

// round 15
// speedup vs baseline: 1.5651x; 1.1484x over previous
#include <cuda_runtime.h>
#include <cuda_bf16.h>

#define BSZ 32
#define TT  200
#define RR  512
#define FF  128
#define BR  4
#define CC  10
#define K2  1024
#define NROWS 2048
#define VTH 0.5f

#define NCTA_TOTAL 148
#define GEMM_CTAS  128
#define NTH 1024

#define KT_STRIDE 36      // floats per kT row (32 batches + pad)
#define ROWSTRIDE 272     // cur section + spk section, each padded to 8
#define OUT0 (BSZ*CC*TT)
#define SLOT (RR*BSZ)     // 16384 floats

// -------- device scratch --------
__device__ float          g_currents[TT * SLOT];       // [T][R][B]
__device__ float          g_projA[TT * NROWS * BSZ];   // [T][row][B] cur-proj
__device__ float          g_ring[4][SLOT];             // epoch-encoded spikes
__device__ unsigned short g_pidx16[NROWS * ROWSTRIDE]; // k*36 (rebased per half)
__device__ float          g_wv [NROWS * ROWSTRIDE];
__device__ unsigned       g_secs[NROWS];               // ncurP | nspkP<<16
__device__ volatile unsigned g_ro[32];                 // readout staged-step+1

__device__ __forceinline__ float sigmoidf_(float x) { return 1.f / (1.f + __expf(-x)); }

__device__ __forceinline__ float4 ldcg4(const float4* p) {
    float4 v;
    asm volatile("ld.global.cg.v4.f32 {%0,%1,%2,%3}, [%4];"
                 : "=f"(v.x), "=f"(v.y), "=f"(v.z), "=f"(v.w) : "l"(p));
    return v;
}

__global__ void k_init() {
    int tid = blockIdx.x * blockDim.x + threadIdx.x;
    for (int i = tid; i < 4 * SLOT; i += gridDim.x * blockDim.x)
        ((float*)g_ring)[i] = (i >= 3 * SLOT) ? 1.0f : 0.0f;  // slot3: S(-1)=0,epoch1
    if (tid < 32) g_ro[tid] = 0;
}

__global__ void k_currents(const float* __restrict__ inp,
                           const float* __restrict__ w_in,
                           const float* __restrict__ b_in) {
    __shared__ float sw[FF];
    int tid = threadIdx.x;
    if (tid < FF) sw[tid] = w_in[tid];
    __syncthreads();
    int lane = tid & 31, wid = tid >> 5;
    long long rid = (long long)blockIdx.x * 8 + wid;
    if (rid >= (long long)BSZ * TT * RR) return;
    const float4* p = (const float4*)inp + rid * (FF / 4);
    float4 v = p[lane];
    float4 w = ((const float4*)sw)[lane];
    float s = v.x * w.x + v.y * w.y + v.z * w.z + v.w * w.w;
    #pragma unroll
    for (int o = 16; o; o >>= 1) s += __shfl_xor_sync(0xffffffffu, s, o);
    if (lane == 0) {
        int r = (int)(rid % RR);
        long long bt = rid / RR;
        int t = (int)(bt % TT);
        int b = (int)(bt / TT);
        g_currents[((long long)t * RR + r) * BSZ + b] = s + b_in[0];
    }
}

// compact rows: cur section (k<512, idx=k*36) then spk section (k>=512, idx=(k-512)*36)
__global__ void k_prep(const float* __restrict__ w_rnn,
                       const float* __restrict__ mask) {
    int row = blockIdx.x * 8 + (threadIdx.x >> 5);
    int lane = threadIdx.x & 31;
    if (row >= NROWS) return;
    unsigned short* pp = g_pidx16 + row * ROWSTRIDE;
    float*          wp = g_wv    + row * ROWSTRIDE;

    int base = 0;
    for (int c0 = 0; c0 < 512; c0 += 32) {
        float m = mask[(long long)row * K2 + c0 + lane];
        unsigned bal = __ballot_sync(0xffffffffu, m != 0.f);
        int pre = __popc(bal & ((1u << lane) - 1u));
        if (m != 0.f) {
            pp[base + pre] = (unsigned short)((c0 + lane) * KT_STRIDE);
            wp[base + pre] = w_rnn[(long long)row * K2 + c0 + lane];
        }
        base += __popc(bal);
    }
    int ncur = base, ncurP = (ncur + 7) & ~7;
    if (lane < ncurP - ncur) { pp[ncur + lane] = 0; wp[ncur + lane] = 0.f; }

    base = 0;
    for (int c0 = 512; c0 < K2; c0 += 32) {
        float m = mask[(long long)row * K2 + c0 + lane];
        unsigned bal = __ballot_sync(0xffffffffu, m != 0.f);
        int pre = __popc(bal & ((1u << lane) - 1u));
        if (m != 0.f) {
            pp[ncurP + base + pre] = (unsigned short)((c0 + lane - 512) * KT_STRIDE);
            wp[ncurP + base + pre] = w_rnn[(long long)row * K2 + c0 + lane];
        }
        base += __popc(bal);
    }
    int nspk = base, nspkP = (nspk + 7) & ~7;
    if (lane < nspkP - nspk) { pp[ncurP + nspk + lane] = 0; wp[ncurP + nspk + lane] = 0.f; }
    if (lane == 0) g_secs[row] = (unsigned)ncurP | ((unsigned)nspkP << 16);
}

// paired sparse GEMM on parity-permuted blocks {e0,e1,e2,e3,o0,o1,o2,o3}.
// lane&15 = batch pair; off4 = 4 for odd-parity lanes (lane>=16).
// One LDS.64 gather per (nnz, 2 batches); warp covers 2 nnz/instr; conflict-free.
__device__ __forceinline__ void gemm_pair(
    const float* wp, const unsigned short* ip, int cnt,
    const char* ktp, int off4, float* dst, int lane)
{
    float a0 = 0.f, a1 = 0.f, b0 = 0.f, b1 = 0.f;
    for (int j = 0; j < cnt; j += 8) {
        float4 w = *(const float4*)(wp + j + off4);
        uint2  q = *(const uint2*)(ip + j + off4);   // 4 u16 of own parity
        unsigned o0 = (q.x & 0xFFFFu) * 4u;
        unsigned o1 = (q.x >> 16) * 4u;
        unsigned o2 = (q.y & 0xFFFFu) * 4u;
        unsigned o3 = (q.y >> 16) * 4u;
        float2 v0 = *(const float2*)(ktp + o0);
        float2 v1 = *(const float2*)(ktp + o1);
        float2 v2 = *(const float2*)(ktp + o2);
        float2 v3 = *(const float2*)(ktp + o3);
        a0 = fmaf(w.x, v0.x, a0); a1 = fmaf(w.x, v0.y, a1);
        b0 = fmaf(w.y, v1.x, b0); b1 = fmaf(w.y, v1.y, b1);
        a0 = fmaf(w.z, v2.x, a0); a1 = fmaf(w.z, v2.y, a1);
        b0 = fmaf(w.w, v3.x, b0); b1 = fmaf(w.w, v3.y, b1);
    }
    a0 += b0; a1 += b1;
    a0 += __shfl_xor_sync(0xffffffffu, a0, 16);
    a1 += __shfl_xor_sync(0xffffffffu, a1, 16);
    if (lane < 16) *(float2*)(dst + lane * 2) = make_float2(a0, a1);
}

// -------- k_proj: projA[t][row][b] for all t (fully parallel) --------------
// CTA = (t-chunk of 8, row-block of 32). Weights staged+permuted once.
__global__ void __launch_bounds__(1024, 1)
k_proj() {
    extern __shared__ float smf[];
    float*          s_w   = smf;                                   // 32*272 f
    unsigned short* s_idx = (unsigned short*)(smf + 32 * ROWSTRIDE);
    float*          s_kT  = smf + 32 * ROWSTRIDE + 16 * ROWSTRIDE; // after idx (u16)

    int tid = threadIdx.x, lane = tid & 31, wid = tid >> 5;
    int rb = blockIdx.x & 63;       // row block
    int tc = blockIdx.x >> 6;       // t chunk
    int row0 = rb * 32;

    for (int i = tid; i < 32 * ROWSTRIDE; i += 1024) {
        int p = i & 7, src = (i & ~7) + ((p < 4) ? 2 * p : 2 * p - 7);
        s_w[i]   = g_wv    [(long long)row0 * ROWSTRIDE + src];
        s_idx[i] = g_pidx16[(long long)row0 * ROWSTRIDE + src];
    }
    __syncthreads();

    const char* ktp = (const char*)s_kT + (lane & 15) * 8;
    int off4 = (lane & 16) ? 4 : 0;
    int row = row0 + wid;
    int ncurP = g_secs[row] & 0xFFFF;

    for (int tt = 0; tt < 8; tt++) {
        int t = tc * 8 + tt;
        const float4* cur = (const float4*)(g_currents + (long long)t * SLOT);
        #pragma unroll
        for (int j = 0; j < 4; j++) {
            int i = tid + j * 1024;
            *(float4*)(s_kT + (i >> 3) * KT_STRIDE + (i & 7) * 4) = __ldg(cur + i);
        }
        __syncthreads();
        gemm_pair(s_w + wid * ROWSTRIDE, s_idx + wid * ROWSTRIDE, ncurP,
                  ktp, off4, g_projA + ((long long)t * NROWS + row) * BSZ, lane);
        __syncthreads();
    }
}

// smem float offsets (GEMM CTAs) — spike-only kT [512][36]
#define SW_OFF   0
#define SI_OFF   (SW_OFF + 16*ROWSTRIDE)           // idx u16: 16*272 = 2176 f
#define KT_OFF   (SI_OFF + 8*ROWSTRIDE)
#define PB_OFF   (KT_OFF + RR*KT_STRIDE)
#define SD_OFF   (PB_OFF + 32*32)
#define SM_OFF   (SD_OFF + 16*33)
#define SS_OFF   (SM_OFF + 4*33)
#define HB_OFF   (SS_OFF + 4*33)
#define BT_OFF   (HB_OFF + 128*9)
#define BN_OFF   (BT_OFF + 16)
#define AL_OFF   (BN_OFF + 16)
#define SEC_OFF  (AL_OFF + 8)
#define SMEM_FLOATS (SEC_OFF + 24)

__global__ void __launch_bounds__(NTH, 1)
k_recurrent(const float* __restrict__ gating,
            const float* __restrict__ b_rnn,
            const float* __restrict__ tau_m,
            const float* __restrict__ tau_n,
            const float* __restrict__ w_ro,
            const float* __restrict__ b_ro,
            const float* __restrict__ tau_m_ro,
            float* __restrict__ out) {
    extern __shared__ float smf[];
    int tid = threadIdx.x, lane = tid & 31, wid = tid >> 5;
    int bid = blockIdx.x;

    if (bid >= GEMM_CTAS) {
        // ======== readout CTAs (20): epoch-poll ring, stage, dot ========
        float* s_wro = smf;
        float* s_sp  = s_wro + CC * RR;
        for (int i = tid; i < CC * RR; i += NTH) s_wro[i] = w_ro[i];
        __syncthreads();

        int task = (bid - GEMM_CTAS) * 32 + wid;
        bool act = task < BSZ * CC;
        int b_ = act ? task / CC : 0, c_ = act ? task % CC : 0;
        float ao = sigmoidf_(tau_m_ro[c_]), bro = b_ro[c_];
        float m0 = 0.f, sp0 = 0.f;
        int myidx = bid - GEMM_CTAS;

        for (int t = 0; t < TT; t++) {
            const float4* slot4 = (const float4*)(g_ring[t & 3]);
            float thr = (float)(t + 2);
            float4 v0, v1, v2, v3;
            for (;;) {
                v0 = ldcg4(slot4 + tid);
                v1 = ldcg4(slot4 + tid + 1024);
                v2 = ldcg4(slot4 + tid + 2048);
                v3 = ldcg4(slot4 + tid + 3072);
                bool ok = v0.x >= thr && v0.y >= thr && v0.z >= thr && v0.w >= thr
                       && v1.x >= thr && v1.y >= thr && v1.z >= thr && v1.w >= thr
                       && v2.x >= thr && v2.y >= thr && v2.z >= thr && v2.w >= thr
                       && v3.x >= thr && v3.y >= thr && v3.z >= thr && v3.w >= thr;
                if (ok) break;
                __nanosleep(40);
            }
            {
                int i0 = tid, r, b4;
                r = i0 >> 3; b4 = (i0 & 7) * 4;
                s_sp[r * 33 + b4] = v0.x - thr; s_sp[r * 33 + b4 + 1] = v0.y - thr;
                s_sp[r * 33 + b4 + 2] = v0.z - thr; s_sp[r * 33 + b4 + 3] = v0.w - thr;
                i0 = tid + 1024; r = i0 >> 3; b4 = (i0 & 7) * 4;
                s_sp[r * 33 + b4] = v1.x - thr; s_sp[r * 33 + b4 + 1] = v1.y - thr;
                s_sp[r * 33 + b4 + 2] = v1.z - thr; s_sp[r * 33 + b4 + 3] = v1.w - thr;
                i0 = tid + 2048; r = i0 >> 3; b4 = (i0 & 7) * 4;
                s_sp[r * 33 + b4] = v2.x - thr; s_sp[r * 33 + b4 + 1] = v2.y - thr;
                s_sp[r * 33 + b4 + 2] = v2.z - thr; s_sp[r * 33 + b4 + 3] = v2.w - thr;
                i0 = tid + 3072; r = i0 >> 3; b4 = (i0 & 7) * 4;
                s_sp[r * 33 + b4] = v3.x - thr; s_sp[r * 33 + b4 + 1] = v3.y - thr;
                s_sp[r * 33 + b4 + 2] = v3.z - thr; s_sp[r * 33 + b4 + 3] = v3.w - thr;
            }
            __syncthreads();
            if (tid == 0) g_ro[myidx] = (unsigned)(t + 1);
            if (act) {
                float sum = 0.f;
                #pragma unroll
                for (int i = 0; i < RR; i += 32)
                    sum += s_sp[(i + lane) * 33 + b_] * s_wro[c_ * RR + i + lane];
                #pragma unroll
                for (int o = 16; o; o >>= 1) sum += __shfl_xor_sync(0xffffffffu, sum, o);
                m0 = m0 * ao + (1.f - ao) * (sum + bro) - VTH * sp0;
                sp0 = (m0 - VTH) > 0.f ? 1.f : 0.f;
                if (lane == 0) out[(long long)task * TT + t] = m0;
            }
            __syncthreads();
        }
        return;
    }

    // ======== GEMM CTAs (128): 16 rows (4 neurons) x 32 batches ========
    float*          s_w    = smf + SW_OFF;
    unsigned short* s_idx  = (unsigned short*)(smf + SI_OFF);
    float*          s_kT   = smf + KT_OFF;           // spike-only [512][36]
    float*          s_pB   = smf + PB_OFF;
    float*          s_d    = smf + SD_OFF;
    float*          s_mem  = smf + SM_OFF;
    float*          s_spk  = smf + SS_OFF;
    float*          s_hist = smf + HB_OFF;
    float*          s_beta = smf + BT_OFF;
    float*          s_brnn = smf + BN_OFF;
    float*          s_alph = smf + AL_OFF;
    unsigned*       s_secs = (unsigned*)(smf + SEC_OFF);

    int row0 = bid * 16, n0 = bid * 4;

    for (int i = tid; i < 16 * ROWSTRIDE; i += NTH) {
        int p = i & 7, src = (i & ~7) + ((p < 4) ? 2 * p : 2 * p - 7);
        s_w[i]   = g_wv    [row0 * ROWSTRIDE + src];
        s_idx[i] = g_pidx16[row0 * ROWSTRIDE + src];
    }
    if (tid < 16) {
        s_secs[tid] = g_secs[row0 + tid];
        s_beta[tid] = sigmoidf_(tau_n[(n0 + (tid >> 2)) * BR + (tid & 3)]);
        s_brnn[tid] = b_rnn[row0 + tid];
    }
    if (tid < 4) s_alph[tid] = sigmoidf_(tau_m[n0 + tid]);
    for (int i = tid; i < 16 * 33; i += NTH) s_d[i] = 0.f;
    if (tid < 4 * 33) { s_mem[tid] = 0.f; s_spk[tid] = 0.f; }
    __syncthreads();

    const char* ktp = (const char*)s_kT + (lane & 15) * 8;
    int off4 = (lane & 16) ? 4 : 0;

    int foff[4];
    #pragma unroll
    for (int j = 0; j < 4; j++) {
        int i = tid + j * 1024;
        foff[j] = (i >> 3) * KT_STRIDE + (i & 7) * 4;
    }

    for (int t = 0; t < TT; t++) {
        // prefetch projA(t) + gating (wid<4: neuron=wid, batch=lane)
        float pj0 = 0.f, pj1 = 0.f, pj2 = 0.f, pj3 = 0.f, gpre = 0.f;
        if (wid < 4) {
            long long pb = ((long long)t * NROWS + row0 + wid * 4) * BSZ + lane;
            pj0 = __ldg(&g_projA[pb]);
            pj1 = __ldg(&g_projA[pb + BSZ]);
            pj2 = __ldg(&g_projA[pb + 2 * BSZ]);
            pj3 = __ldg(&g_projA[pb + 3 * BSZ]);
            gpre = __ldg(&gating[((long long)lane * TT + t) * RR + n0 + wid]);
        }

        // (B) poll-fill S(t-1) from ring slot (t-1)&3 (epoch >= t+1)
        {
            const float4* slot4 = (const float4*)(g_ring[(t + 3) & 3]);
            float thr = (float)(t + 1);
            float4 v0, v1, v2, v3;
            for (;;) {
                v0 = ldcg4(slot4 + tid);
                v1 = ldcg4(slot4 + tid + 1024);
                v2 = ldcg4(slot4 + tid + 2048);
                v3 = ldcg4(slot4 + tid + 3072);
                bool ok = v0.x >= thr && v0.y >= thr && v0.z >= thr && v0.w >= thr
                       && v1.x >= thr && v1.y >= thr && v1.z >= thr && v1.w >= thr
                       && v2.x >= thr && v2.y >= thr && v2.z >= thr && v2.w >= thr
                       && v3.x >= thr && v3.y >= thr && v3.z >= thr && v3.w >= thr;
                if (ok) break;
                __nanosleep(40);
            }
            v0.x -= thr; v0.y -= thr; v0.z -= thr; v0.w -= thr;
            v1.x -= thr; v1.y -= thr; v1.z -= thr; v1.w -= thr;
            v2.x -= thr; v2.y -= thr; v2.z -= thr; v2.w -= thr;
            v3.x -= thr; v3.y -= thr; v3.z -= thr; v3.w -= thr;
            *(float4*)(s_kT + foff[0]) = v0;
            *(float4*)(s_kT + foff[1]) = v1;
            *(float4*)(s_kT + foff[2]) = v2;
            *(float4*)(s_kT + foff[3]) = v3;
        }
        __syncthreads();

        // (C) spike GEMM -> s_pB (warp = half row, paired gathers)
        {
            int row = wid >> 1, half = wid & 1;
            unsigned sec = s_secs[row];
            int ncurP = sec & 0xFFFF, nspkP = sec >> 16;
            int h0 = (nspkP >> 4) << 3;
            int beg = ncurP + (half ? h0 : 0);
            int cnt = half ? (nspkP - h0) : h0;
            gemm_pair(s_w + row * ROWSTRIDE + beg, s_idx + row * ROWSTRIDE + beg,
                      cnt, ktp, off4, s_pB + (half * 16 + row) * 32, lane);
        }
        __syncthreads();

        // (D) wid<4: phase3, publish S(t) epoch t+2 | wid27: readout-lag guard
        if (wid < 4) {
            int nl = wid, b = lane;
            float g = gpre;
            float lin = 0.f;
            #pragma unroll
            for (int br = 0; br < BR; br++) {
                int row = nl * 4 + br;
                float pj = br == 0 ? pj0 : br == 1 ? pj1 : br == 2 ? pj2 : pj3;
                float proj = pj + s_pB[row * 32 + b] + s_pB[(16 + row) * 32 + b]
                           + s_brnn[row];
                float beta = s_beta[row];
                float dold = s_d[row * 33 + b];
                float dnew = beta * dold + (1.f - beta) * proj;
                lin += dnew;
                s_d[row * 33 + b] = g * dnew + (1.f - g) * dold;
            }
            float alpha = s_alph[nl];
            float mold = s_mem[nl * 33 + b];
            float sold = s_spk[nl * 33 + b];
            float mnew = mold * alpha + (1.f - alpha) * lin - VTH * sold;
            float snew = (mnew - VTH) > 0.f ? 1.f : 0.f;
            float mg = g * mnew + (1.f - g) * mold;
            float sg = g * snew + (1.f - g) * sold;
            __stcg(&g_ring[t & 3][(n0 + nl) * BSZ + b], sg + (float)(t + 2));
            s_mem[nl * 33 + b] = mg;
            s_spk[nl * 33 + b] = sg;
            s_hist[(nl * 32 + b) * 9 + (t & 7)] = sg;
            if ((t & 7) == 7) {
                const float* h = s_hist + (nl * 32 + b) * 9;
                float4 w0 = make_float4(h[0], h[1], h[2], h[3]);
                float4 w1 = make_float4(h[4], h[5], h[6], h[7]);
                long long base = OUT0 + ((long long)b * RR + (n0 + nl)) * TT + (t - 7);
                *(float4*)(out + base) = w0;
                *(float4*)(out + base + 4) = w1;
            }
        } else if (wid == 27 && t >= 2) {
            if (lane < 20) {
                while (g_ro[lane] < (unsigned)(t - 2)) __nanosleep(40);
            }
            __syncwarp();
        }
        // no trailing sync: (B)-end sync next iteration covers pB/kT hazards
    }
}

extern "C" void kernel_launch(void* const* d_in, const int* in_sizes, int n_in,
                              void* d_out, int out_size) {
    const float* inp      = (const float*)d_in[0];
    const float* gating   = (const float*)d_in[1];
    const float* w_in     = (const float*)d_in[2];
    const float* b_in     = (const float*)d_in[3];
    const float* w_rnn    = (const float*)d_in[4];
    const float* b_rnn    = (const float*)d_in[5];
    const float* tau_m    = (const float*)d_in[6];
    const float* tau_n    = (const float*)d_in[7];
    const float* w_ro     = (const float*)d_in[8];
    const float* b_ro     = (const float*)d_in[9];
    const float* tau_m_ro = (const float*)d_in[10];
    const float* mask     = (const float*)d_in[11];
    float* out = (float*)d_out;

    int smem_rec = SMEM_FLOATS * 4 + 256;                   // ~112 KB
    cudaFuncSetAttribute(k_recurrent,
                         cudaFuncAttributeMaxDynamicSharedMemorySize, smem_rec);
    int smem_proj = (48 * ROWSTRIDE + RR * KT_STRIDE) * 4 + 256;  // ~126 KB
    cudaFuncSetAttribute(k_proj,
                         cudaFuncAttributeMaxDynamicSharedMemorySize, smem_proj);

    k_init<<<64, 256>>>();

    long long total_rows = (long long)BSZ * TT * RR;
    int gridA = (int)((total_rows + 7) / 8);
    k_currents<<<gridA, 256>>>(inp, w_in, b_in);

    k_prep<<<NROWS / 8, 256>>>(w_rnn, mask);

    k_proj<<<64 * 25, 1024, smem_proj>>>();

    k_recurrent<<<NCTA_TOTAL, NTH, smem_rec>>>(gating, b_rnn, tau_m, tau_n,
                                               w_ro, b_ro, tau_m_ro, out);
}

// round 16
// speedup vs baseline: 1.7902x; 1.1438x over previous
#include <cuda_runtime.h>
#include <cuda_bf16.h>

#define BSZ 32
#define TT  200
#define RR  512
#define FF  128
#define BR  4
#define CC  10
#define K2  1024
#define NROWS 2048
#define VTH 0.5f

#define NCTA_TOTAL 148
#define GEMM_CTAS  128
#define NTH 1024

#define KT_STRIDE 36      // floats per spike-kT row
#define ROWSTRIDE 272     // cur section + spk section, each padded to 8
#define OUT0 (BSZ*CC*TT)
#define SLOT (RR*BSZ)     // 16384 floats
#define AHEAD 8           // cur-proj lookahead
#define RINGP 9           // pA ring depth (> AHEAD)

// -------- device scratch --------
__device__ float          g_currents[TT * SLOT];       // [T][R][B]
__device__ float          g_ring[4][SLOT];             // epoch-encoded spikes
__device__ unsigned short g_pidx16[NROWS * ROWSTRIDE]; // cur: k ; spk: (k-512)*36
__device__ float          g_wv [NROWS * ROWSTRIDE];
__device__ unsigned       g_secs[NROWS];               // ncurP | nspkP<<16
__device__ volatile unsigned g_ro[32];                 // readout staged-step+1

__device__ __forceinline__ float sigmoidf_(float x) { return 1.f / (1.f + __expf(-x)); }

__device__ __forceinline__ float4 ldcg4(const float4* p) {
    float4 v;
    asm volatile("ld.global.cg.v4.f32 {%0,%1,%2,%3}, [%4];"
                 : "=f"(v.x), "=f"(v.y), "=f"(v.z), "=f"(v.w) : "l"(p));
    return v;
}

__global__ void k_init() {
    int tid = blockIdx.x * blockDim.x + threadIdx.x;
    for (int i = tid; i < 4 * SLOT; i += gridDim.x * blockDim.x)
        ((float*)g_ring)[i] = (i >= 3 * SLOT) ? 1.0f : 0.0f;  // slot3: S(-1)=0,epoch1
    if (tid < 32) g_ro[tid] = 0;
}

__global__ void k_currents(const float* __restrict__ inp,
                           const float* __restrict__ w_in,
                           const float* __restrict__ b_in) {
    __shared__ float sw[FF];
    int tid = threadIdx.x;
    if (tid < FF) sw[tid] = w_in[tid];
    __syncthreads();
    int lane = tid & 31, wid = tid >> 5;
    long long rid = (long long)blockIdx.x * 8 + wid;
    if (rid >= (long long)BSZ * TT * RR) return;
    const float4* p = (const float4*)inp + rid * (FF / 4);
    float4 v = p[lane];
    float4 w = ((const float4*)sw)[lane];
    float s = v.x * w.x + v.y * w.y + v.z * w.z + v.w * w.w;
    #pragma unroll
    for (int o = 16; o; o >>= 1) s += __shfl_xor_sync(0xffffffffu, s, o);
    if (lane == 0) {
        int r = (int)(rid % RR);
        long long bt = rid / RR;
        int t = (int)(bt % TT);
        int b = (int)(bt / TT);
        g_currents[((long long)t * RR + r) * BSZ + b] = s + b_in[0];
    }
}

// compact rows: cur section (k<512, idx=k) then spk section (k>=512, idx=(k-512)*36)
__global__ void k_prep(const float* __restrict__ w_rnn,
                       const float* __restrict__ mask) {
    int row = blockIdx.x * 8 + (threadIdx.x >> 5);
    int lane = threadIdx.x & 31;
    if (row >= NROWS) return;
    unsigned short* pp = g_pidx16 + row * ROWSTRIDE;
    float*          wp = g_wv    + row * ROWSTRIDE;

    int base = 0;
    for (int c0 = 0; c0 < 512; c0 += 32) {
        float m = mask[(long long)row * K2 + c0 + lane];
        unsigned bal = __ballot_sync(0xffffffffu, m != 0.f);
        int pre = __popc(bal & ((1u << lane) - 1u));
        if (m != 0.f) {
            pp[base + pre] = (unsigned short)(c0 + lane);
            wp[base + pre] = w_rnn[(long long)row * K2 + c0 + lane];
        }
        base += __popc(bal);
    }
    int ncur = base, ncurP = (ncur + 7) & ~7;
    if (lane < ncurP - ncur) { pp[ncur + lane] = 0; wp[ncur + lane] = 0.f; }

    base = 0;
    for (int c0 = 512; c0 < K2; c0 += 32) {
        float m = mask[(long long)row * K2 + c0 + lane];
        unsigned bal = __ballot_sync(0xffffffffu, m != 0.f);
        int pre = __popc(bal & ((1u << lane) - 1u));
        if (m != 0.f) {
            pp[ncurP + base + pre] = (unsigned short)((c0 + lane - 512) * KT_STRIDE);
            wp[ncurP + base + pre] = w_rnn[(long long)row * K2 + c0 + lane];
        }
        base += __popc(bal);
    }
    int nspk = base, nspkP = (nspk + 7) & ~7;
    if (lane < nspkP - nspk) { pp[ncurP + nspk + lane] = 0; wp[ncurP + nspk + lane] = 0.f; }
    if (lane == 0) g_secs[row] = (unsigned)ncurP | ((unsigned)nspkP << 16);
}

// paired sparse GEMM (smem kT, spikes). Parity-permuted blocks {e0..e3,o0..o3}.
__device__ __forceinline__ void gemm_pair(
    const float* wp, const unsigned short* ip, int cnt,
    const char* ktp, int off4, float* dst, int lane)
{
    float a0 = 0.f, a1 = 0.f, b0 = 0.f, b1 = 0.f;
    for (int j = 0; j < cnt; j += 8) {
        float4 w = *(const float4*)(wp + j + off4);
        uint2  q = *(const uint2*)(ip + j + off4);
        unsigned o0 = (q.x & 0xFFFFu) * 4u;
        unsigned o1 = (q.x >> 16) * 4u;
        unsigned o2 = (q.y & 0xFFFFu) * 4u;
        unsigned o3 = (q.y >> 16) * 4u;
        float2 v0 = *(const float2*)(ktp + o0);
        float2 v1 = *(const float2*)(ktp + o1);
        float2 v2 = *(const float2*)(ktp + o2);
        float2 v3 = *(const float2*)(ktp + o3);
        a0 = fmaf(w.x, v0.x, a0); a1 = fmaf(w.x, v0.y, a1);
        b0 = fmaf(w.y, v1.x, b0); b1 = fmaf(w.y, v1.y, b1);
        a0 = fmaf(w.z, v2.x, a0); a1 = fmaf(w.z, v2.y, a1);
        b0 = fmaf(w.w, v3.x, b0); b1 = fmaf(w.w, v3.y, b1);
    }
    a0 += b0; a1 += b1;
    a0 += __shfl_xor_sync(0xffffffffu, a0, 16);
    a1 += __shfl_xor_sync(0xffffffffu, a1, 16);
    if (lane < 16) *(float2*)(dst + lane * 2) = make_float2(a0, a1);
}

// paired sparse GEMM gathering currents straight from GMEM via L1.
// cb = row base for this lane's batch pair; idx u16 = k; line offset = k<<7.
__device__ __forceinline__ void gemm_pair_g(
    const float* wp, const unsigned short* ip, int cnt,
    const char* cb, int off4, float* dst, int lane)
{
    float a0 = 0.f, a1 = 0.f, b0 = 0.f, b1 = 0.f;
    for (int j = 0; j < cnt; j += 8) {
        float4 w = *(const float4*)(wp + j + off4);
        uint2  q = *(const uint2*)(ip + j + off4);
        float2 v0 = __ldg((const float2*)(cb + ((q.x & 0xFFFFu) << 7)));
        float2 v1 = __ldg((const float2*)(cb + ((q.x >> 16) << 7)));
        float2 v2 = __ldg((const float2*)(cb + ((q.y & 0xFFFFu) << 7)));
        float2 v3 = __ldg((const float2*)(cb + ((q.y >> 16) << 7)));
        a0 = fmaf(w.x, v0.x, a0); a1 = fmaf(w.x, v0.y, a1);
        b0 = fmaf(w.y, v1.x, b0); b1 = fmaf(w.y, v1.y, b1);
        a0 = fmaf(w.z, v2.x, a0); a1 = fmaf(w.z, v2.y, a1);
        b0 = fmaf(w.w, v3.x, b0); b1 = fmaf(w.w, v3.y, b1);
    }
    a0 += b0; a1 += b1;
    a0 += __shfl_xor_sync(0xffffffffu, a0, 16);
    a1 += __shfl_xor_sync(0xffffffffu, a1, 16);
    if (lane < 16) *(float2*)(dst + lane * 2) = make_float2(a0, a1);
}

// smem float offsets (GEMM CTAs)
#define SW_OFF   0
#define SI_OFF   (SW_OFF + 16*ROWSTRIDE)           // u16: 16*272 = 2176 f
#define KT_OFF   (SI_OFF + 8*ROWSTRIDE)
#define PA_OFF   (KT_OFF + RR*KT_STRIDE)           // pA ring: RINGP * 1024 f
#define PB_OFF   (PA_OFF + RINGP*1024)
#define SD_OFF   (PB_OFF + 1024)
#define SM_OFF   (SD_OFF + 16*33)
#define SS_OFF   (SM_OFF + 4*33)
#define HB_OFF   (SS_OFF + 4*33)
#define BT_OFF   (HB_OFF + 128*9)
#define BN_OFF   (BT_OFF + 16)
#define AL_OFF   (BN_OFF + 16)
#define SEC_OFF  (AL_OFF + 8)
#define SMEM_FLOATS (SEC_OFF + 24)

__global__ void __launch_bounds__(NTH, 1)
k_recurrent(const float* __restrict__ gating,
            const float* __restrict__ b_rnn,
            const float* __restrict__ tau_m,
            const float* __restrict__ tau_n,
            const float* __restrict__ w_ro,
            const float* __restrict__ b_ro,
            const float* __restrict__ tau_m_ro,
            float* __restrict__ out) {
    extern __shared__ float smf[];
    int tid = threadIdx.x, lane = tid & 31, wid = tid >> 5;
    int bid = blockIdx.x;

    if (bid >= GEMM_CTAS) {
        // ======== readout CTAs (20): epoch-poll ring, stage, dot ========
        float* s_wro = smf;
        float* s_sp  = s_wro + CC * RR;
        for (int i = tid; i < CC * RR; i += NTH) s_wro[i] = w_ro[i];
        __syncthreads();

        int task = (bid - GEMM_CTAS) * 32 + wid;
        bool act = task < BSZ * CC;
        int b_ = act ? task / CC : 0, c_ = act ? task % CC : 0;
        float ao = sigmoidf_(tau_m_ro[c_]), bro = b_ro[c_];
        float m0 = 0.f, sp0 = 0.f;
        int myidx = bid - GEMM_CTAS;

        for (int t = 0; t < TT; t++) {
            const float4* slot4 = (const float4*)(g_ring[t & 3]);
            float thr = (float)(t + 2);
            float4 v0, v1, v2, v3;
            for (;;) {
                v0 = ldcg4(slot4 + tid);
                v1 = ldcg4(slot4 + tid + 1024);
                v2 = ldcg4(slot4 + tid + 2048);
                v3 = ldcg4(slot4 + tid + 3072);
                bool ok = v0.x >= thr && v0.y >= thr && v0.z >= thr && v0.w >= thr
                       && v1.x >= thr && v1.y >= thr && v1.z >= thr && v1.w >= thr
                       && v2.x >= thr && v2.y >= thr && v2.z >= thr && v2.w >= thr
                       && v3.x >= thr && v3.y >= thr && v3.z >= thr && v3.w >= thr;
                if (ok) break;
                __nanosleep(40);
            }
            {
                int i0 = tid, r, b4;
                r = i0 >> 3; b4 = (i0 & 7) * 4;
                s_sp[r * 33 + b4] = v0.x - thr; s_sp[r * 33 + b4 + 1] = v0.y - thr;
                s_sp[r * 33 + b4 + 2] = v0.z - thr; s_sp[r * 33 + b4 + 3] = v0.w - thr;
                i0 = tid + 1024; r = i0 >> 3; b4 = (i0 & 7) * 4;
                s_sp[r * 33 + b4] = v1.x - thr; s_sp[r * 33 + b4 + 1] = v1.y - thr;
                s_sp[r * 33 + b4 + 2] = v1.z - thr; s_sp[r * 33 + b4 + 3] = v1.w - thr;
                i0 = tid + 2048; r = i0 >> 3; b4 = (i0 & 7) * 4;
                s_sp[r * 33 + b4] = v2.x - thr; s_sp[r * 33 + b4 + 1] = v2.y - thr;
                s_sp[r * 33 + b4 + 2] = v2.z - thr; s_sp[r * 33 + b4 + 3] = v2.w - thr;
                i0 = tid + 3072; r = i0 >> 3; b4 = (i0 & 7) * 4;
                s_sp[r * 33 + b4] = v3.x - thr; s_sp[r * 33 + b4 + 1] = v3.y - thr;
                s_sp[r * 33 + b4 + 2] = v3.z - thr; s_sp[r * 33 + b4 + 3] = v3.w - thr;
            }
            __syncthreads();
            if (tid == 0) g_ro[myidx] = (unsigned)(t + 1);
            if (act) {
                float sum = 0.f;
                #pragma unroll
                for (int i = 0; i < RR; i += 32)
                    sum += s_sp[(i + lane) * 33 + b_] * s_wro[c_ * RR + i + lane];
                #pragma unroll
                for (int o = 16; o; o >>= 1) sum += __shfl_xor_sync(0xffffffffu, sum, o);
                m0 = m0 * ao + (1.f - ao) * (sum + bro) - VTH * sp0;
                sp0 = (m0 - VTH) > 0.f ? 1.f : 0.f;
                if (lane == 0) out[(long long)task * TT + t] = m0;
            }
            __syncthreads();
        }
        return;
    }

    // ======== GEMM CTAs (128): 16 rows (4 neurons) x 32 batches ========
    float*          s_w    = smf + SW_OFF;
    unsigned short* s_idx  = (unsigned short*)(smf + SI_OFF);
    float*          s_kT   = smf + KT_OFF;           // spike-only [512][36]
    float*          s_pA   = smf + PA_OFF;           // ring RINGP x (2x16x32)
    float*          s_pB   = smf + PB_OFF;
    float*          s_d    = smf + SD_OFF;
    float*          s_mem  = smf + SM_OFF;
    float*          s_spk  = smf + SS_OFF;
    float*          s_hist = smf + HB_OFF;
    float*          s_beta = smf + BT_OFF;
    float*          s_brnn = smf + BN_OFF;
    float*          s_alph = smf + AL_OFF;
    unsigned*       s_secs = (unsigned*)(smf + SEC_OFF);

    int row0 = bid * 16, n0 = bid * 4;

    for (int i = tid; i < 16 * ROWSTRIDE; i += NTH) {
        int p = i & 7, src = (i & ~7) + ((p < 4) ? 2 * p : 2 * p - 7);
        s_w[i]   = g_wv    [row0 * ROWSTRIDE + src];
        s_idx[i] = g_pidx16[row0 * ROWSTRIDE + src];
    }
    if (tid < 16) {
        s_secs[tid] = g_secs[row0 + tid];
        s_beta[tid] = sigmoidf_(tau_n[(n0 + (tid >> 2)) * BR + (tid & 3)]);
        s_brnn[tid] = b_rnn[row0 + tid];
    }
    if (tid < 4) s_alph[tid] = sigmoidf_(tau_m[n0 + tid]);
    for (int i = tid; i < 16 * 33; i += NTH) s_d[i] = 0.f;
    if (tid < 4 * 33) { s_mem[tid] = 0.f; s_spk[tid] = 0.f; }
    __syncthreads();

    const char* ktp  = (const char*)s_kT + (lane & 15) * 8;
    int off4 = (lane & 16) ? 4 : 0;
    int lboff = (lane & 15) * 8;     // byte offset of batch pair within a currents row

    int foff[4];
    #pragma unroll
    for (int j = 0; j < 4; j++) {
        int i = tid + j * 1024;
        foff[j] = (i >> 3) * KT_STRIDE + (i & 7) * 4;
    }

    // per-warp GEMM split (cur section)
    int rowW = wid >> 1, halfW = wid & 1;
    unsigned secW = s_secs[rowW];
    int ncurPW = (int)(secW & 0xFFFF), nspkPW = (int)(secW >> 16);
    int hc = (ncurPW >> 4) << 3;
    int begC = halfW ? hc : 0;
    int cntC = halfW ? (ncurPW - hc) : hc;
    int hs = (nspkPW >> 4) << 3;
    int begS = ncurPW + (halfW ? hs : 0);
    int cntS = halfW ? (nspkPW - hs) : hs;
    const float*          wpC = s_w   + rowW * ROWSTRIDE + begC;
    const unsigned short* ipC = s_idx + rowW * ROWSTRIDE + begC;
    const float*          wpS = s_w   + rowW * ROWSTRIDE + begS;
    const unsigned short* ipS = s_idx + rowW * ROWSTRIDE + begS;
    int dstOff = halfW * 512 + rowW * 32;

    // prologue: cur-proj for t = 0..AHEAD-1 into ring slots 0..7
    for (int j = 0; j < AHEAD; j++) {
        const char* cb = (const char*)(g_currents + (long long)j * SLOT) + lboff;
        gemm_pair_g(wpC, ipC, cntC, cb, off4, s_pA + j * 1024 + dstOff, lane);
    }
    __syncthreads();

    int sR = 0, sW = AHEAD;   // ring read/write slots (mod RINGP)

    for (int t = 0; t < TT; t++) {
        float gpre = 0.f;
        if (wid < 4)
            gpre = __ldg(&gating[((long long)lane * TT + t) * RR + n0 + wid]);

        // (B) poll-fill S(t-1) from ring slot (t-1)&3 (epoch >= t+1)
        {
            const float4* slot4 = (const float4*)(g_ring[(t + 3) & 3]);
            float thr = (float)(t + 1);
            float4 v0, v1, v2, v3;
            for (;;) {
                v0 = ldcg4(slot4 + tid);
                v1 = ldcg4(slot4 + tid + 1024);
                v2 = ldcg4(slot4 + tid + 2048);
                v3 = ldcg4(slot4 + tid + 3072);
                bool ok = v0.x >= thr && v0.y >= thr && v0.z >= thr && v0.w >= thr
                       && v1.x >= thr && v1.y >= thr && v1.z >= thr && v1.w >= thr
                       && v2.x >= thr && v2.y >= thr && v2.z >= thr && v2.w >= thr
                       && v3.x >= thr && v3.y >= thr && v3.z >= thr && v3.w >= thr;
                if (ok) break;
                __nanosleep(40);
            }
            v0.x -= thr; v0.y -= thr; v0.z -= thr; v0.w -= thr;
            v1.x -= thr; v1.y -= thr; v1.z -= thr; v1.w -= thr;
            v2.x -= thr; v2.y -= thr; v2.z -= thr; v2.w -= thr;
            v3.x -= thr; v3.y -= thr; v3.z -= thr; v3.w -= thr;
            *(float4*)(s_kT + foff[0]) = v0;
            *(float4*)(s_kT + foff[1]) = v1;
            *(float4*)(s_kT + foff[2]) = v2;
            *(float4*)(s_kT + foff[3]) = v3;
        }
        __syncthreads();

        // (C1) spike GEMM -> s_pB
        gemm_pair(wpS, ipS, cntS, ktp, off4, s_pB + dstOff, lane);
        __syncthreads();

        // (D) wid<4: phase3 + publish; wid27: readout guard; then all: C2
        if (wid < 4) {
            int nl = wid, b = lane;
            const float* pA = s_pA + sR * 1024;
            float g = gpre;
            float lin = 0.f;
            #pragma unroll
            for (int br = 0; br < BR; br++) {
                int row = nl * 4 + br;
                float proj = pA[row * 32 + b] + pA[512 + row * 32 + b]
                           + s_pB[row * 32 + b] + s_pB[512 + row * 32 + b]
                           + s_brnn[row];
                float beta = s_beta[row];
                float dold = s_d[row * 33 + b];
                float dnew = beta * dold + (1.f - beta) * proj;
                lin += dnew;
                s_d[row * 33 + b] = g * dnew + (1.f - g) * dold;
            }
            float alpha = s_alph[nl];
            float mold = s_mem[nl * 33 + b];
            float sold = s_spk[nl * 33 + b];
            float mnew = mold * alpha + (1.f - alpha) * lin - VTH * sold;
            float snew = (mnew - VTH) > 0.f ? 1.f : 0.f;
            float mg = g * mnew + (1.f - g) * mold;
            float sg = g * snew + (1.f - g) * sold;
            __stcg(&g_ring[t & 3][(n0 + nl) * BSZ + b], sg + (float)(t + 2));
            s_mem[nl * 33 + b] = mg;
            s_spk[nl * 33 + b] = sg;
            s_hist[(nl * 32 + b) * 9 + (t & 7)] = sg;
            if ((t & 7) == 7) {
                const float* h = s_hist + (nl * 32 + b) * 9;
                float4 w0 = make_float4(h[0], h[1], h[2], h[3]);
                float4 w1 = make_float4(h[4], h[5], h[6], h[7]);
                long long base = OUT0 + ((long long)b * RR + (n0 + nl)) * TT + (t - 7);
                *(float4*)(out + base) = w0;
                *(float4*)(out + base + 4) = w1;
            }
        } else if (wid == 27 && t >= 2) {
            if (lane < 20) {
                while (g_ro[lane] < (unsigned)(t - 2)) __nanosleep(40);
            }
            __syncwarp();
        }

        // (C2) cur-proj for t+AHEAD into ring slot sW (slack work, off crit path)
        if (t + AHEAD < TT) {
            const char* cb = (const char*)(g_currents + (long long)(t + AHEAD) * SLOT)
                           + lboff;
            gemm_pair_g(wpC, ipC, cntC, cb, off4, s_pA + sW * 1024 + dstOff, lane);
        }
        if (++sR == RINGP) sR = 0;
        if (++sW == RINGP) sW = 0;
        // no trailing sync: next (B)-end sync orders pA/pB/kT reuse
    }
}

extern "C" void kernel_launch(void* const* d_in, const int* in_sizes, int n_in,
                              void* d_out, int out_size) {
    const float* inp      = (const float*)d_in[0];
    const float* gating   = (const float*)d_in[1];
    const float* w_in     = (const float*)d_in[2];
    const float* b_in     = (const float*)d_in[3];
    const float* w_rnn    = (const float*)d_in[4];
    const float* b_rnn    = (const float*)d_in[5];
    const float* tau_m    = (const float*)d_in[6];
    const float* tau_n    = (const float*)d_in[7];
    const float* w_ro     = (const float*)d_in[8];
    const float* b_ro     = (const float*)d_in[9];
    const float* tau_m_ro = (const float*)d_in[10];
    const float* mask     = (const float*)d_in[11];
    float* out = (float*)d_out;

    int smem_rec = SMEM_FLOATS * 4 + 256;   // ~154 KB (readout path needs ~88 KB)
    cudaFuncSetAttribute(k_recurrent,
                         cudaFuncAttributeMaxDynamicSharedMemorySize, smem_rec);

    k_init<<<64, 256>>>();

    long long total_rows = (long long)BSZ * TT * RR;
    int gridA = (int)((total_rows + 7) / 8);
    k_currents<<<gridA, 256>>>(inp, w_in, b_in);

    k_prep<<<NROWS / 8, 256>>>(w_rnn, mask);

    k_recurrent<<<NCTA_TOTAL, NTH, smem_rec>>>(gating, b_rnn, tau_m, tau_n,
                                               w_ro, b_ro, tau_m_ro, out);
}